// round 14
// baseline (speedup 1.0000x reference)
#include <cuda_runtime.h>
#include <cuda_bf16.h>
#include <math.h>
#include <stdint.h>

#define BB 16
#define CC 32
#define NN 512
#define T1 192
#define T2 96
#define L1 97
#define L2 49
#define EE 64

typedef unsigned long long ull;
typedef __nv_bfloat16 bf16;

static constexpr size_t SZ1 = (size_t)BB*CC*NN*T1;
static constexpr size_t SZ2 = (size_t)BB*CC*NN*T2;

// ---------------- scratch ----------------
__device__ float g_bufA[SZ1];
__device__ float g_bufB[SZ1];
__device__ float g_bufC[SZ1];
__device__ float g_bufD[SZ2];
__device__ float g_bufF[SZ2];
__device__ float g_Mc[CC*T1*T1];
__device__ float g_Mt[CC*T1*T1];
__device__ float g_D1[CC*T1*T2];
__device__ float g_C2[CC*T2*T2];
__device__ float g_cos1[L1*T1];
__device__ float g_sin1[L1*T1];
__device__ float g_cos2[L2*T2];
__device__ float g_sin2[L2*T2];
__device__ float g_K1[CC*T1];
__device__ float g_K2[CC*T2];
__device__ float g_featP[BB*CC*8*T1];
__device__ float g_gate[BB*T1];
// pre-split bf16 weights
__device__ bf16 g_Bin[2*4*192*T1];           // input layers [layer][mat:W1h,W1l,W2h,W2l][n=192][k=192]
__device__ bf16 g_Bout[2*1*4*96*T2];         // output layers (old layout)
__device__ bf16 g_McB[CC*2*192*384];
__device__ bf16 g_D1B[CC*2*96*T1];
__device__ bf16 g_C2B[CC*2*96*T2];

// ---------------- f32x2 helpers ----------------
__device__ __forceinline__ ull pk2(float lo, float hi) {
    ull r; asm("mov.b64 %0, {%1,%2};" : "=l"(r) : "f"(lo), "f"(hi)); return r;
}
__device__ __forceinline__ void fma2(ull& d, ull a, ull b) {
    asm("fma.rn.f32x2 %0, %1, %2, %0;" : "+l"(d) : "l"(a), "l"(b));
}
__device__ __forceinline__ float2 upk2(ull v) {
    float2 f; asm("mov.b64 {%0,%1}, %2;" : "=f"(f.x), "=f"(f.y) : "l"(v)); return f;
}

__device__ __forceinline__ float gelu_t(float x) {
    float x3 = x*x*x;
    return 0.5f*x*(1.0f + tanhf(0.7978845608028654f*(x + 0.044715f*x3)));
}

__device__ __forceinline__ uint32_t smem_u32(const void* p) {
    uint32_t a;
    asm("{ .reg .u64 t; cvta.to.shared.u64 t, %1; cvt.u32.u64 %0, t; }" : "=r"(a) : "l"(p));
    return a;
}

// ---------------- mma.sync helpers ----------------
#define LDM4(r, addr) \
    asm volatile("ldmatrix.sync.aligned.m8n8.x4.shared.b16 {%0,%1,%2,%3}, [%4];" \
        : "=r"((r)[0]), "=r"((r)[1]), "=r"((r)[2]), "=r"((r)[3]) : "r"(addr))

#define MMA_BF16(c, a, b0, b1) \
    asm volatile("mma.sync.aligned.m16n8k16.row.col.f32.bf16.bf16.f32 " \
        "{%0,%1,%2,%3},{%4,%5,%6,%7},{%8,%9},{%0,%1,%2,%3};" \
        : "+f"((c)[0]), "+f"((c)[1]), "+f"((c)[2]), "+f"((c)[3]) \
        : "r"((a)[0]), "r"((a)[1]), "r"((a)[2]), "r"((a)[3]), "r"(b0), "r"(b1))

__device__ __forceinline__ void cvt_hilo_store(float4 v0, float4 v1, bf16* dH, bf16* dL) {
    __nv_bfloat162 h0 = __floats2bfloat162_rn(v0.x, v0.y);
    __nv_bfloat162 h1 = __floats2bfloat162_rn(v0.z, v0.w);
    __nv_bfloat162 h2 = __floats2bfloat162_rn(v1.x, v1.y);
    __nv_bfloat162 h3 = __floats2bfloat162_rn(v1.z, v1.w);
    __nv_bfloat162 l0 = __floats2bfloat162_rn(v0.x - __bfloat162float(h0.x), v0.y - __bfloat162float(h0.y));
    __nv_bfloat162 l1 = __floats2bfloat162_rn(v0.z - __bfloat162float(h1.x), v0.w - __bfloat162float(h1.y));
    __nv_bfloat162 l2 = __floats2bfloat162_rn(v1.x - __bfloat162float(h2.x), v1.y - __bfloat162float(h2.y));
    __nv_bfloat162 l3 = __floats2bfloat162_rn(v1.z - __bfloat162float(h3.x), v1.w - __bfloat162float(h3.y));
    *(uint4*)dH = make_uint4(*(uint32_t*)&h0, *(uint32_t*)&h1, *(uint32_t*)&h2, *(uint32_t*)&h3);
    *(uint4*)dL = make_uint4(*(uint32_t*)&l0, *(uint32_t*)&l1, *(uint32_t*)&l2, *(uint32_t*)&l3);
}

__device__ __forceinline__ void cvt_hilo4(float4 v, bf16* dH, bf16* dL) {
    __nv_bfloat162 h0 = __floats2bfloat162_rn(v.x, v.y);
    __nv_bfloat162 h1 = __floats2bfloat162_rn(v.z, v.w);
    __nv_bfloat162 l0 = __floats2bfloat162_rn(v.x - __bfloat162float(h0.x), v.y - __bfloat162float(h0.y));
    __nv_bfloat162 l1 = __floats2bfloat162_rn(v.z - __bfloat162float(h1.x), v.w - __bfloat162float(h1.y));
    *(uint2*)dH = make_uint2(*(uint32_t*)&h0, *(uint32_t*)&h1);
    *(uint2*)dL = make_uint2(*(uint32_t*)&l0, *(uint32_t*)&l1);
}

// ---------------- precompute ----------------
__global__ void k_tables() {
    int i = blockIdx.x*blockDim.x + threadIdx.x;
    if (i < L1*T1) {
        int h = i / T1, t = i % T1;
        int m = (h*t) % T1;
        float a = (float)m * (1.0f/96.0f);
        g_cos1[i] = cospif(a);
        g_sin1[i] = sinpif(a);
    }
    int j = i - L1*T1;
    if (j >= 0 && j < L2*T2) {
        int h = j / T2, t = j % T2;
        int m = (h*t) % T2;
        float a = (float)m * (1.0f/48.0f);
        g_cos2[j] = cospif(a);
        g_sin2[j] = sinpif(a);
    }
}

__global__ void k_buildM(const float* __restrict__ Lc, const float* __restrict__ Lt) {
    int t = blockIdx.x, l = blockIdx.y, tp = threadIdx.x;
    float ac = 0.f, as = 0.f;
    for (int h = 0; h < L1; h++) {
        float w = (h == 0 || h == L1-1) ? (1.0f/T1) : (2.0f/T1);
        float lc = Lc[l*L1+h]*w, lt = Lt[l*L1+h]*w;
        ac = fmaf(lc * g_cos1[h*T1+t], g_cos1[h*T1+tp], ac);
        as = fmaf(lt * g_sin1[h*T1+t], g_sin1[h*T1+tp], as);
    }
    size_t o = ((size_t)l*T1 + t)*T1 + tp;
    g_Mc[o] = ac;
    g_Mt[o] = as;
}

__global__ void k_buildK1(const float* __restrict__ Wr, const float* __restrict__ Wi) {
    int i = blockIdx.x*blockDim.x + threadIdx.x;
    if (i >= CC*T1) return;
    int c = i / T1, d = i % T1;
    float acc = 0.f;
    for (int h = 0; h < L1; h++) {
        float w = (h == 0 || h == L1-1) ? (1.0f/T1) : (2.0f/T1);
        acc += w * (Wr[c*L1+h]*g_cos1[h*T1+d] - Wi[c*L1+h]*g_sin1[h*T1+d]);
    }
    g_K1[i] = acc;
}

__global__ void k_buildD1(const float* __restrict__ Wfc) {
    __shared__ float kr[2*T1];
    int t = blockIdx.x, c = blockIdx.y, s2 = threadIdx.x;
    for (int s = s2; s < T1; s += T2) {
        float v = g_K1[c*T1 + s];
        kr[s] = v; kr[s + T1] = v;
    }
    __syncthreads();
    float acc = 0.f;
    const float* kb = kr + (T1 - t);
    for (int s = 0; s < T1; s++)
        acc = fmaf(kb[s], Wfc[s*T2 + s2], acc);
    g_D1[((size_t)c*T1 + t)*T2 + s2] = acc;
}

__global__ void k_buildK2(const float* __restrict__ Wr, const float* __restrict__ Wi) {
    int i = blockIdx.x*blockDim.x + threadIdx.x;
    if (i >= CC*T2) return;
    int c = i / T2, d = i % T2;
    float acc = 0.f;
    for (int h = 0; h < L2; h++) {
        float w = (h == 0 || h == L2-1) ? (1.0f/T2) : (2.0f/T2);
        acc += w * (Wr[c*L2+h]*g_cos2[h*T2+d] - Wi[c*L2+h]*g_sin2[h*T2+d]);
    }
    g_K2[i] = acc;
}
__global__ void k_expand2() {
    size_t i = (size_t)blockIdx.x*blockDim.x + threadIdx.x;
    if (i >= (size_t)CC*T2*T2) return;
    int s = (int)(i % T2);
    int t = (int)((i / T2) % T2);
    int c = (int)(i / ((size_t)T2*T2));
    g_C2[i] = g_K2[c*T2 + ((s - t + T2) % T2)];
}

// input-layer weights: [layer][mat:W1h,W1l,W2h,W2l][n=192][k=192]
__global__ void k_splitWF(const float* __restrict__ W1, const float* __restrict__ W2,
                          bf16* __restrict__ dst) {
    int total = 2*4*192*T1;
    int idx = blockIdx.x*blockDim.x + threadIdx.x;
    if (idx >= total) return;
    int k     = idx % T1;
    int n     = (idx / T1) % 192;
    int mat   = (idx / (T1*192)) % 4;
    int layer = idx / (T1*192*4);
    const float* src = (mat < 2) ? W1 : W2;
    float w = src[(size_t)layer*T1*T1 + (size_t)k*T1 + n];
    bf16 hi = __float2bfloat16(w);
    bf16 v = (mat & 1) ? __float2bfloat16(w - __bfloat162float(hi)) : hi;
    dst[idx] = v;
}

// output-layer weights (old layout): [layer][half=1][mat][96][96]
template<int KTOT, int HALVES>
__global__ void k_splitW(const float* __restrict__ W1, const float* __restrict__ W2,
                         bf16* __restrict__ dst) {
    int total = 2*HALVES*4*96*KTOT;
    int idx = blockIdx.x*blockDim.x + threadIdx.x;
    if (idx >= total) return;
    int k     = idx % KTOT;
    int n     = (idx / KTOT) % 96;
    int mat   = (idx / (KTOT*96)) % 4;
    int half  = (idx / (KTOT*96*4)) % HALVES;
    int layer = idx / (KTOT*96*4*HALVES);
    const float* src = (mat < 2) ? W1 : W2;
    int s = half*96 + n;
    float w = src[(size_t)layer*KTOT*KTOT + (size_t)k*KTOT + s];
    bf16 hi = __float2bfloat16(w);
    bf16 v = (mat & 1) ? __float2bfloat16(w - __bfloat162float(hi)) : hi;
    dst[idx] = v;
}

__global__ void k_splitMM() {
    size_t total = (size_t)CC*2*192*384;
    size_t idx = (size_t)blockIdx.x*blockDim.x + threadIdx.x;
    if (idx >= total) return;
    int k     = (int)(idx % 384);
    int n     = (int)((idx / 384) % 192);
    int plane = (int)((idx / (384*192)) % 2);
    int c     = (int)(idx / (384*192*2));
    float w = (k < 192) ? g_Mc[((size_t)c*T1 + k)*T1 + n]
                        : g_Mt[((size_t)c*T1 + (k-192))*T1 + n];
    bf16 hi = __float2bfloat16(w);
    g_McB[idx] = plane ? __float2bfloat16(w - __bfloat162float(hi)) : hi;
}

__global__ void k_splitD1() {
    int total = CC*2*96*T1;
    int idx = blockIdx.x*blockDim.x + threadIdx.x;
    if (idx >= total) return;
    int k     = idx % T1;
    int n     = (idx / T1) % 96;
    int plane = (idx / (T1*96)) % 2;
    int c     = idx / (T1*96*2);
    float w = g_D1[((size_t)c*T1 + k)*T2 + n];
    bf16 hi = __float2bfloat16(w);
    g_D1B[idx] = plane ? __float2bfloat16(w - __bfloat162float(hi)) : hi;
}

__global__ void k_splitC2() {
    int total = CC*2*96*T2;
    int idx = blockIdx.x*blockDim.x + threadIdx.x;
    if (idx >= total) return;
    int k     = idx % T2;
    int n     = (idx / T2) % 96;
    int plane = (idx / (T2*96)) % 2;
    int c     = idx / (T2*96*2);
    float w = g_C2[((size_t)c*T2 + k)*T2 + n];
    bf16 hi = __float2bfloat16(w);
    g_C2B[idx] = plane ? __float2bfloat16(w - __bfloat162float(hi)) : hi;
}

// ---------------- channel mix ----------------
__global__ void __launch_bounds__(256) k_chmix(const float* __restrict__ x,
                                               const float* __restrict__ Gc,
                                               const float* __restrict__ Gt) {
    __shared__ __align__(16) float2 sG[CC*CC];
    int tid = threadIdx.x;
    for (int i = tid; i < CC*CC; i += 256) sG[i] = make_float2(Gc[i], Gt[i]);
    __syncthreads();
    int b = blockIdx.y;
    size_t m = (size_t)blockIdx.x*256 + tid;
    ull a[CC];
#pragma unroll
    for (int l = 0; l < CC; l++) a[l] = 0ull;
    for (int c = 0; c < CC; c++) {
        float xv = x[((size_t)(b*CC + c)*NN)*T1 + m];
        ull xp = pk2(xv, xv);
#pragma unroll
        for (int l = 0; l < CC; l++) fma2(a[l], xp, *(const ull*)&sG[c*CC + l]);
    }
#pragma unroll
    for (int l = 0; l < CC; l++) {
        float2 p = upk2(a[l]);
        g_bufA[((size_t)(b*CC + l)*NN)*T1 + m] = p.x;
        g_bufB[((size_t)(b*CC + l)*NN)*T1 + m] = p.y;
    }
}

// ---------------- mm2 (tensor, merged N=192): Y = resid + [u|v] @ [Mc;Mt][c] ----------------
__global__ void __launch_bounds__(256) k_mm2MMA(const float* __restrict__ U,
                                                const float* __restrict__ V,
                                                const float* __restrict__ resid,
                                                float* __restrict__ Y) {
    constexpr int AST = 40;
    __shared__ __align__(16) bf16 sAh[64*AST];
    __shared__ __align__(16) bf16 sAl[64*AST];
    __shared__ __align__(16) bf16 sB[2*192*AST];
    int tid = threadIdx.x, lane = tid & 31, wid = tid >> 5;
    int wm = wid & 3, wn = wid >> 2;
    int c = blockIdx.y, b = blockIdx.z;
    size_t row0 = (size_t)(b*CC + c)*NN + (size_t)blockIdx.x*64;
    const bf16* Wc = g_McB + (size_t)c*2*192*384;

    float cc[12][4];
#pragma unroll
    for (int i = 0; i < 12; i++)
#pragma unroll
        for (int j = 0; j < 4; j++) cc[i][j] = 0.f;

    uint32_t aOff = (uint32_t)((wm*16 + (lane & 15))*AST + ((lane >> 4) << 3)) * 2;
    uint32_t aAddrH = smem_u32(sAh) + aOff;
    uint32_t aAddrL = smem_u32(sAl) + aOff;
    uint32_t bRow = (uint32_t)((lane & 7) + ((lane >> 4) << 3));
    uint32_t bOff = (bRow*AST + (((lane >> 3) & 1) << 3)) * 2;
    uint32_t sBbase = smem_u32(sB);

    int arow = tid >> 2, akg = (tid & 3) * 8;
    bf16* aDstH = &sAh[arow*AST + akg];
    bf16* aDstL = &sAl[arow*AST + akg];

    float4 nx0, nx1;
    uint4 nB[6];
    {
        const float* xr = U + (row0 + arow)*T1 + akg;
        nx0 = *(const float4*)xr; nx1 = *(const float4*)(xr + 4);
#pragma unroll
        for (int it = 0; it < 6; it++) {
            int i = tid + it*256;
            int plane = i / 768, rem = i % 768;
            int n = rem >> 2, kg = (rem & 3) * 8;
            nB[it] = *(const uint4*)&Wc[((size_t)plane*192 + n)*384 + kg];
        }
    }
    for (int kc = 0; kc < 12; kc++) {
        cvt_hilo_store(nx0, nx1, aDstH, aDstL);
#pragma unroll
        for (int it = 0; it < 6; it++) {
            int i = tid + it*256;
            int plane = i / 768, rem = i % 768;
            int n = rem >> 2, kg = (rem & 3) * 8;
            *(uint4*)&sB[(plane*192 + n)*AST + kg] = nB[it];
        }
        __syncthreads();
        if (kc + 1 < 12) {
            int kn = kc + 1;
            const float* Xs = (kn < 6) ? U : V;
            int kl = (kn < 6) ? kn : kn - 6;
            const float* xr = Xs + (row0 + arow)*T1 + kl*32 + akg;
            nx0 = *(const float4*)xr; nx1 = *(const float4*)(xr + 4);
#pragma unroll
            for (int it = 0; it < 6; it++) {
                int i = tid + it*256;
                int plane = i / 768, rem = i % 768;
                int n = rem >> 2, kg = (rem & 3) * 8;
                nB[it] = *(const uint4*)&Wc[((size_t)plane*192 + n)*384 + kn*32 + kg];
            }
        }
#pragma unroll
        for (int k16 = 0; k16 < 2; k16++) {
            uint32_t kof = (uint32_t)(k16 * 32);
            uint32_t ah[4], al[4];
            LDM4(ah, aAddrH + kof);
            LDM4(al, aAddrL + kof);
            uint32_t baseH = sBbase + bOff + kof;
            uint32_t baseL = baseH + (uint32_t)(192*AST)*2;
#pragma unroll
            for (int pr = 0; pr < 6; pr++) {
                uint32_t po = (uint32_t)((wn*96 + pr*16)*AST)*2;
                uint32_t bh[4], bl[4];
                LDM4(bh, baseH + po);
                LDM4(bl, baseL + po);
                MMA_BF16(cc[2*pr],   ah, bh[0], bh[1]);
                MMA_BF16(cc[2*pr+1], ah, bh[2], bh[3]);
                MMA_BF16(cc[2*pr],   al, bh[0], bh[1]);
                MMA_BF16(cc[2*pr+1], al, bh[2], bh[3]);
                MMA_BF16(cc[2*pr],   ah, bl[0], bl[1]);
                MMA_BF16(cc[2*pr+1], ah, bl[2], bl[3]);
            }
        }
        __syncthreads();
    }

    int g = lane >> 2, tg = lane & 3;
    size_t mrow = row0 + (size_t)wm*16 + g;
    int colb = wn*96 + tg*2;
#pragma unroll
    for (int nf = 0; nf < 12; nf++) {
        int col = colb + nf*8;
        float2 r0 = *(const float2*)&resid[mrow*T1 + col];
        float2 r1 = *(const float2*)&resid[(mrow + 8)*T1 + col];
        *(float2*)&Y[mrow*T1 + col]       = make_float2(cc[nf][0] + r0.x, cc[nf][1] + r0.y);
        *(float2*)&Y[(mrow + 8)*T1 + col] = make_float2(cc[nf][2] + r1.x, cc[nf][3] + r1.y);
    }
}

// ---------------- channel GEMM (tensor): Y = (X1 + sg*X2) @ W[c] [+bias] ----------------
template<int KTOT, bool BIAS>
__global__ void __launch_bounds__(256) k_cgemmMMA(const float* __restrict__ X1,
                                                  const float* __restrict__ X2,
                                                  const bf16* __restrict__ WB,
                                                  const float* __restrict__ bias,
                                                  const float* __restrict__ gate,
                                                  float* __restrict__ Y) {
    constexpr int AST = 40, KC = KTOT/32;
    __shared__ __align__(16) bf16 sAh[64*AST];
    __shared__ __align__(16) bf16 sAl[64*AST];
    __shared__ __align__(16) bf16 sB[2*96*AST];
    __shared__ float sg[KTOT];
    int tid = threadIdx.x, lane = tid & 31, wid = tid >> 5;
    int wm = wid & 3, wn = wid >> 2;
    int c = blockIdx.y, b = blockIdx.z;
    size_t row0 = (size_t)(b*CC + c)*NN + (size_t)blockIdx.x*64;
    const bf16* Wc = WB + (size_t)c*2*96*KTOT;

    for (int t = tid; t < KTOT; t += 256) sg[t] = 1.0f + gate[b*KTOT + t];
    __syncthreads();

    float cc[6][4];
#pragma unroll
    for (int i = 0; i < 6; i++)
#pragma unroll
        for (int j = 0; j < 4; j++) cc[i][j] = 0.f;

    uint32_t aOff = (uint32_t)((wm*16 + (lane & 15))*AST + ((lane >> 4) << 3)) * 2;
    uint32_t aAddrH = smem_u32(sAh) + aOff;
    uint32_t aAddrL = smem_u32(sAl) + aOff;
    uint32_t bRow = (uint32_t)(wn*48 + (lane & 7) + ((lane >> 4) << 3));
    uint32_t bOff = (bRow*AST + (((lane >> 3) & 1) << 3)) * 2;
    uint32_t sBbase = smem_u32(sB);

    int arow = tid >> 2, akg = (tid & 3) * 8;
    const float* x1r = X1 + (row0 + arow)*KTOT;
    const float* x2r = X2 + (row0 + arow)*KTOT;
    bf16* aDstH = &sAh[arow*AST + akg];
    bf16* aDstL = &sAl[arow*AST + akg];

    float4 na0, na1, nb0, nb1;
    uint4 nB[3];
    {
        na0 = *(const float4*)&x1r[akg];
        na1 = *(const float4*)&x1r[akg + 4];
        nb0 = *(const float4*)&x2r[akg];
        nb1 = *(const float4*)&x2r[akg + 4];
#pragma unroll
        for (int it = 0; it < 3; it++) {
            int i = tid + it*256;
            int plane = i / 384, rem = i % 384;
            int n = rem >> 2, kg = (rem & 3) * 8;
            nB[it] = *(const uint4*)&Wc[((size_t)plane*96 + n)*KTOT + kg];
        }
    }
    for (int kc = 0; kc < KC; kc++) {
        {
            int k0 = kc*32 + akg;
            float4 v0 = na0, v1 = na1;
            v0.x = fmaf(nb0.x, sg[k0],   v0.x);
            v0.y = fmaf(nb0.y, sg[k0+1], v0.y);
            v0.z = fmaf(nb0.z, sg[k0+2], v0.z);
            v0.w = fmaf(nb0.w, sg[k0+3], v0.w);
            v1.x = fmaf(nb1.x, sg[k0+4], v1.x);
            v1.y = fmaf(nb1.y, sg[k0+5], v1.y);
            v1.z = fmaf(nb1.z, sg[k0+6], v1.z);
            v1.w = fmaf(nb1.w, sg[k0+7], v1.w);
            cvt_hilo_store(v0, v1, aDstH, aDstL);
#pragma unroll
            for (int it = 0; it < 3; it++) {
                int i = tid + it*256;
                int plane = i / 384, rem = i % 384;
                int n = rem >> 2, kg = (rem & 3) * 8;
                *(uint4*)&sB[(plane*96 + n)*AST + kg] = nB[it];
            }
        }
        __syncthreads();
        if (kc + 1 < KC) {
            int kn = (kc + 1)*32 + akg;
            na0 = *(const float4*)&x1r[kn];
            na1 = *(const float4*)&x1r[kn + 4];
            nb0 = *(const float4*)&x2r[kn];
            nb1 = *(const float4*)&x2r[kn + 4];
#pragma unroll
            for (int it = 0; it < 3; it++) {
                int i = tid + it*256;
                int plane = i / 384, rem = i % 384;
                int n = rem >> 2, kg = (rem & 3) * 8;
                nB[it] = *(const uint4*)&Wc[((size_t)plane*96 + n)*KTOT + (kc+1)*32 + kg];
            }
        }
#pragma unroll
        for (int k16 = 0; k16 < 2; k16++) {
            uint32_t kof = (uint32_t)(k16 * 32);
            uint32_t ah[4], al[4];
            LDM4(ah, aAddrH + kof);
            LDM4(al, aAddrL + kof);
            uint32_t baseH = sBbase + bOff + kof;
            uint32_t baseL = baseH + (uint32_t)(96*AST)*2;
#pragma unroll
            for (int pr = 0; pr < 3; pr++) {
                uint32_t po = (uint32_t)(pr*16*AST)*2;
                uint32_t bh[4], bl[4];
                LDM4(bh, baseH + po);
                LDM4(bl, baseL + po);
                MMA_BF16(cc[2*pr],   ah, bh[0], bh[1]);
                MMA_BF16(cc[2*pr+1], ah, bh[2], bh[3]);
                MMA_BF16(cc[2*pr],   al, bh[0], bh[1]);
                MMA_BF16(cc[2*pr+1], al, bh[2], bh[3]);
                MMA_BF16(cc[2*pr],   ah, bl[0], bl[1]);
                MMA_BF16(cc[2*pr+1], ah, bl[2], bl[3]);
            }
        }
        __syncthreads();
    }

    int g = lane >> 2, tg = lane & 3;
    size_t mrow = row0 + (size_t)wm*16 + g;
    int colb = wn*48 + tg*2;
#pragma unroll
    for (int nf = 0; nf < 6; nf++) {
        int col = colb + nf*8;
        float2 o0 = make_float2(cc[nf][0], cc[nf][1]);
        float2 o1 = make_float2(cc[nf][2], cc[nf][3]);
        if (BIAS) {
            float2 bv = *(const float2*)&bias[col];
            o0.x += bv.x; o0.y += bv.y; o1.x += bv.x; o1.y += bv.y;
        }
        *(float2*)&Y[mrow*96 + col]       = o0;
        *(float2*)&Y[(mrow + 8)*96 + col] = o1;
    }
}

// ---------------- T1 gmlp: 512 threads, M=64, full N=192, X read once ----------------
// smem: sAh@0 (5120), sAl@5120 (5120), sB@10240 (61440), sg@71680 (768), sFP@72448 (3072) => 75520
template<bool G1>
__global__ void __launch_bounds__(512) k_gmlpF(const float* __restrict__ X,
                                               const bf16* __restrict__ Bw,
                                               const float* __restrict__ gate,
                                               float* __restrict__ Y) {
    constexpr int KTOT = T1, KC = 6, AST = 40;
    extern __shared__ char sm[];
    bf16* sAh = (bf16*)sm;
    bf16* sAl = (bf16*)(sm + 5120);
    bf16* sB  = (bf16*)(sm + 10240);
    float* sg = (float*)(sm + 71680);
    float (*sFP)[48] = (float(*)[48])(sm + 72448);
    int tid = threadIdx.x, lane = tid & 31, wid = tid >> 5;
    int wm = wid & 3, wn = wid >> 2;     // 4M x 4N
    int tix = blockIdx.x;
    size_t row0 = (size_t)tix * 64;
    int b = tix >> 8, ch = (tix >> 3) & 31, tile = tix & 7;

    if (G1) {
        for (int t = tid; t < KTOT; t += 512) sg[t] = 1.0f + gate[b*KTOT + t];
        __syncthreads();
    }

    float c1[6][4], c2[6][4];
#pragma unroll
    for (int i = 0; i < 6; i++)
#pragma unroll
        for (int j = 0; j < 4; j++) { c1[i][j] = 0.f; c2[i][j] = 0.f; }

    uint32_t aOff = (uint32_t)((wm*16 + (lane & 15))*AST + ((lane >> 4) << 3)) * 2;
    uint32_t aAddrH = smem_u32(sAh) + aOff;
    uint32_t aAddrL = smem_u32(sAl) + aOff;
    uint32_t bRow = (uint32_t)(wn*48 + (lane & 7) + ((lane >> 4) << 3));
    uint32_t bOff = (bRow*AST + (((lane >> 3) & 1) << 3)) * 2;
    uint32_t sBbase = smem_u32(sB);

    int arow = tid >> 3, akg = (tid & 7) * 4;     // 64 rows x 8 thr x 4 elems
    const float* xrow = X + (row0 + arow)*KTOT;
    bf16* aDstH = &sAh[arow*AST + akg];
    bf16* aDstL = &sAl[arow*AST + akg];

    float4 nx;
    uint4 nB[6];
    {
        nx = *(const float4*)&xrow[akg];
#pragma unroll
        for (int it = 0; it < 6; it++) {
            int i = tid + it*512;
            int mat = i / 768, rem = i % 768;
            int n = rem >> 2, kg = (rem & 3) * 8;
            nB[it] = *(const uint4*)&Bw[((size_t)mat*192 + n)*KTOT + kg];
        }
    }
    for (int kc = 0; kc < KC; kc++) {
        {
            int k0 = kc*32 + akg;
            float4 v = nx;
            if (G1) { v.x *= sg[k0]; v.y *= sg[k0+1]; v.z *= sg[k0+2]; v.w *= sg[k0+3]; }
            cvt_hilo4(v, aDstH, aDstL);
#pragma unroll
            for (int it = 0; it < 6; it++) {
                int i = tid + it*512;
                int mat = i / 768, rem = i % 768;
                int n = rem >> 2, kg = (rem & 3) * 8;
                *(uint4*)&sB[(mat*192 + n)*AST + kg] = nB[it];
            }
        }
        __syncthreads();
        if (kc + 1 < KC) {
            int kn = (kc + 1)*32;
            nx = *(const float4*)&xrow[kn + akg];
#pragma unroll
            for (int it = 0; it < 6; it++) {
                int i = tid + it*512;
                int mat = i / 768, rem = i % 768;
                int n = rem >> 2, kg = (rem & 3) * 8;
                nB[it] = *(const uint4*)&Bw[((size_t)mat*192 + n)*KTOT + kn + kg];
            }
        }
#pragma unroll
        for (int k16 = 0; k16 < 2; k16++) {
            uint32_t kof = (uint32_t)(k16 * 32);
            uint32_t ah[4], al[4];
            LDM4(ah, aAddrH + kof);
            LDM4(al, aAddrL + kof);
#pragma unroll
            for (int mat = 0; mat < 2; mat++) {
                float (*cf)[4] = mat ? c2 : c1;
                uint32_t baseH = sBbase + (uint32_t)((mat*2 + 0)*192*AST)*2 + bOff + kof;
                uint32_t baseL = sBbase + (uint32_t)((mat*2 + 1)*192*AST)*2 + bOff + kof;
#pragma unroll
                for (int pr = 0; pr < 3; pr++) {
                    uint32_t po = (uint32_t)(pr*16*AST)*2;
                    uint32_t bh[4], bl[4];
                    LDM4(bh, baseH + po);
                    LDM4(bl, baseL + po);
                    MMA_BF16(cf[2*pr],   ah, bh[0], bh[1]);
                    MMA_BF16(cf[2*pr+1], ah, bh[2], bh[3]);
                    MMA_BF16(cf[2*pr],   al, bh[0], bh[1]);
                    MMA_BF16(cf[2*pr+1], al, bh[2], bh[3]);
                    MMA_BF16(cf[2*pr],   ah, bl[0], bl[1]);
                    MMA_BF16(cf[2*pr+1], ah, bl[2], bl[3]);
                }
            }
        }
        __syncthreads();
    }

    // epilogue: o = (X@W1)*gelu(X@W2), store + column partial sums
    int g = lane >> 2, tg = lane & 3;
    size_t mrow = row0 + (size_t)wm*16 + g;
    int colb = wn*48 + tg*2;
    float colsum[12];
#pragma unroll
    for (int nf = 0; nf < 6; nf++) {
        int col = colb + nf*8;
        float2 o0 = make_float2(c1[nf][0]*gelu_t(c2[nf][0]), c1[nf][1]*gelu_t(c2[nf][1]));
        float2 o1 = make_float2(c1[nf][2]*gelu_t(c2[nf][2]), c1[nf][3]*gelu_t(c2[nf][3]));
        *(float2*)&Y[mrow*KTOT + col] = o0;
        *(float2*)&Y[(mrow + 8)*KTOT + col] = o1;
        colsum[2*nf]   = o0.x + o1.x;
        colsum[2*nf+1] = o0.y + o1.y;
    }
#pragma unroll
    for (int i = 0; i < 12; i++) {
        float v = colsum[i];
        v += __shfl_xor_sync(0xFFFFFFFF, v, 16);
        v += __shfl_xor_sync(0xFFFFFFFF, v, 8);
        v += __shfl_xor_sync(0xFFFFFFFF, v, 4);
        colsum[i] = v;
    }
    if (lane < 4) {
#pragma unroll
        for (int nf = 0; nf < 6; nf++) {
            sFP[wid][lane*2 + nf*8]     = colsum[2*nf];
            sFP[wid][lane*2 + nf*8 + 1] = colsum[2*nf+1];
        }
    }
    __syncthreads();
    if (tid < 192) {
        int wn2 = tid / 48, idx = tid % 48;
        float tot = sFP[wn2*4+0][idx] + sFP[wn2*4+1][idx] + sFP[wn2*4+2][idx] + sFP[wn2*4+3][idx];
        g_featP[((size_t)(b*CC + ch)*8 + tile)*KTOT + tid] = tot;
    }
}

// ---------------- T2 gmlp (M=64, R11 shape, HALVES=1) + fused n-mean ----------------
template<int KTOT, bool G1>
__global__ void __launch_bounds__(256) k_gmlpMMA(const float* __restrict__ X,
                                                 const bf16* __restrict__ Bw,
                                                 const float* __restrict__ gate,
                                                 float* __restrict__ Y) {
    constexpr int KC = KTOT/32;
    constexpr int AST = 40;
    __shared__ __align__(16) bf16 sAh[64*AST];
    __shared__ __align__(16) bf16 sAl[64*AST];
    __shared__ __align__(16) bf16 sB[4*96*AST];
    __shared__ float sg[KTOT];
    __shared__ float sFP[8][48];
    int tid = threadIdx.x, lane = tid & 31, wid = tid >> 5;
    int wm = wid & 3, wn = wid >> 2;
    int tix = blockIdx.x;
    size_t row0 = (size_t)tix * 64;
    int b = tix >> 8;
    int ch = (tix >> 3) & 31;
    int tile = tix & 7;
    const bf16* BwH = Bw;

    if (G1) {
        for (int t = tid; t < KTOT; t += 256) sg[t] = 1.0f + gate[b*KTOT + t];
        __syncthreads();
    }

    float c1[6][4], c2[6][4];
#pragma unroll
    for (int i = 0; i < 6; i++)
#pragma unroll
        for (int j = 0; j < 4; j++) { c1[i][j] = 0.f; c2[i][j] = 0.f; }

    uint32_t aOff = (uint32_t)((wm*16 + (lane & 15))*AST + ((lane >> 4) << 3)) * 2;
    uint32_t aAddrH = smem_u32(sAh) + aOff;
    uint32_t aAddrL = smem_u32(sAl) + aOff;
    uint32_t bRow = (uint32_t)(wn*48 + (lane & 7) + ((lane >> 4) << 3));
    uint32_t bOff = (bRow*AST + (((lane >> 3) & 1) << 3)) * 2;
    uint32_t sBbase = smem_u32(sB);

    int arow = tid >> 2, akg = (tid & 3) * 8;
    const float* xrow = X + (row0 + arow)*KTOT;
    bf16* aDstH = &sAh[arow*AST + akg];
    bf16* aDstL = &sAl[arow*AST + akg];

    float4 nx0, nx1;
    uint4 nB[6];
    {
        nx0 = *(const float4*)&xrow[akg];
        nx1 = *(const float4*)&xrow[akg + 4];
#pragma unroll
        for (int it = 0; it < 6; it++) {
            int i = tid + it*256;
            int mat = i / 384, rem = i % 384;
            int n = rem >> 2, kg = (rem & 3) * 8;
            nB[it] = *(const uint4*)&BwH[((size_t)mat*96 + n)*KTOT + kg];
        }
    }
    for (int kc = 0; kc < KC; kc++) {
        {
            int k0 = kc*32 + akg;
            float4 v0 = nx0, v1 = nx1;
            if (G1) {
                v0.x *= sg[k0];   v0.y *= sg[k0+1]; v0.z *= sg[k0+2]; v0.w *= sg[k0+3];
                v1.x *= sg[k0+4]; v1.y *= sg[k0+5]; v1.z *= sg[k0+6]; v1.w *= sg[k0+7];
            }
            cvt_hilo_store(v0, v1, aDstH, aDstL);
#pragma unroll
            for (int it = 0; it < 6; it++) {
                int i = tid + it*256;
                int mat = i / 384, rem = i % 384;
                int n = rem >> 2, kg = (rem & 3) * 8;
                *(uint4*)&sB[(mat*96 + n)*AST + kg] = nB[it];
            }
        }
        __syncthreads();
        if (kc + 1 < KC) {
            int kn = (kc + 1)*32;
            nx0 = *(const float4*)&xrow[kn + akg];
            nx1 = *(const float4*)&xrow[kn + akg + 4];
#pragma unroll
            for (int it = 0; it < 6; it++) {
                int i = tid + it*256;
                int mat = i / 384, rem = i % 384;
                int n = rem >> 2, kg = (rem & 3) * 8;
                nB[it] = *(const uint4*)&BwH[((size_t)mat*96 + n)*KTOT + kn + kg];
            }
        }
#pragma unroll
        for (int k16 = 0; k16 < 2; k16++) {
            uint32_t kof = (uint32_t)(k16 * 32);
            uint32_t ah[4], al[4];
            LDM4(ah, aAddrH + kof);
            LDM4(al, aAddrL + kof);
#pragma unroll
            for (int mat = 0; mat < 2; mat++) {
                float (*cf)[4] = mat ? c2 : c1;
                uint32_t baseH = sBbase + (uint32_t)((mat*2 + 0)*96*AST)*2 + bOff + kof;
                uint32_t baseL = sBbase + (uint32_t)((mat*2 + 1)*96*AST)*2 + bOff + kof;
#pragma unroll
                for (int pr = 0; pr < 3; pr++) {
                    uint32_t po = (uint32_t)(pr*16*AST)*2;
                    uint32_t bh[4], bl[4];
                    LDM4(bh, baseH + po);
                    LDM4(bl, baseL + po);
                    MMA_BF16(cf[2*pr],   ah, bh[0], bh[1]);
                    MMA_BF16(cf[2*pr+1], ah, bh[2], bh[3]);
                    MMA_BF16(cf[2*pr],   al, bh[0], bh[1]);
                    MMA_BF16(cf[2*pr+1], al, bh[2], bh[3]);
                    MMA_BF16(cf[2*pr],   ah, bl[0], bl[1]);
                    MMA_BF16(cf[2*pr+1], ah, bl[2], bl[3]);
                }
            }
        }
        __syncthreads();
    }

    int g = lane >> 2, tg = lane & 3;
    size_t mrow = row0 + (size_t)wm*16 + g;
    int colb = wn*48 + tg*2;
    float colsum[12];
#pragma unroll
    for (int nf = 0; nf < 6; nf++) {
        int col = colb + nf*8;
        float2 o0 = make_float2(c1[nf][0]*gelu_t(c2[nf][0]), c1[nf][1]*gelu_t(c2[nf][1]));
        float2 o1 = make_float2(c1[nf][2]*gelu_t(c2[nf][2]), c1[nf][3]*gelu_t(c2[nf][3]));
        *(float2*)&Y[mrow*KTOT + col] = o0;
        *(float2*)&Y[(mrow + 8)*KTOT + col] = o1;
        colsum[2*nf]   = o0.x + o1.x;
        colsum[2*nf+1] = o0.y + o1.y;
    }
#pragma unroll
    for (int i = 0; i < 12; i++) {
        float v = colsum[i];
        v += __shfl_xor_sync(0xFFFFFFFF, v, 16);
        v += __shfl_xor_sync(0xFFFFFFFF, v, 8);
        v += __shfl_xor_sync(0xFFFFFFFF, v, 4);
        colsum[i] = v;
    }
    if (lane < 4) {
#pragma unroll
        for (int nf = 0; nf < 6; nf++) {
            sFP[wid][lane*2 + nf*8]     = colsum[2*nf];
            sFP[wid][lane*2 + nf*8 + 1] = colsum[2*nf+1];
        }
    }
    __syncthreads();
    if (tid < 96) {
        int wn2 = tid / 48, idx = tid % 48;
        float tot = sFP[wn2*4+0][idx] + sFP[wn2*4+1][idx] + sFP[wn2*4+2][idx] + sFP[wn2*4+3][idx];
        g_featP[((size_t)(b*CC + ch)*8 + tile)*KTOT + wn2*48 + idx] = tot;
    }
}

// ---------------- attn gate (reads featP partials, 8 tiles) ----------------
template<int T>
__global__ void __launch_bounds__(T) k_gate(const float* __restrict__ Wq,
                                            const float* __restrict__ Wk) {
    __shared__ float ks[T][EE];
    int b = blockIdx.x, t = threadIdx.x;
    float q[EE], kk[EE];
#pragma unroll
    for (int e = 0; e < EE; e++) { q[e] = 0.f; kk[e] = 0.f; }
    for (int c = 0; c < CC; c++) {
        float f = 0.f;
#pragma unroll
        for (int p = 0; p < 8; p++) f += g_featP[((size_t)(b*CC + c)*8 + p)*T + t];
        f *= (1.0f/NN);
#pragma unroll
        for (int e = 0; e < EE; e++) {
            q[e]  = fmaf(f, Wq[c*EE + e], q[e]);
            kk[e] = fmaf(f, Wk[c*EE + e], kk[e]);
        }
    }
#pragma unroll
    for (int e = 0; e < EE; e++) ks[t][e] = kk[e];
    __syncthreads();
    float smax = -1e30f, stt = 0.f;
    for (int j = 0; j < T; j++) {
        float d = 0.f;
#pragma unroll
        for (int e = 0; e < EE; e++) d = fmaf(q[e], ks[j][e], d);
        d *= 0.125f;
        if (j == t) stt = d;
        smax = fmaxf(smax, d);
    }
    float ssum = 0.f;
    for (int j = 0; j < T; j++) {
        float d = 0.f;
#pragma unroll
        for (int e = 0; e < EE; e++) d = fmaf(q[e], ks[j][e], d);
        ssum += expf(d*0.125f - smax);
    }
    float p = expf(stt - smax) / ssum;
    g_gate[b*T + t] = gelu_t(p);
}

// ---------------- driver ----------------
extern "C" void kernel_launch(void* const* d_in, const int* in_sizes, int n_in,
                              void* d_out, int out_size) {
    const float* x   = (const float*)d_in[0];
    const float* Gc  = (const float*)d_in[3];
    const float* Lc  = (const float*)d_in[4];
    const float* Gt  = (const float*)d_in[5];
    const float* Lt  = (const float*)d_in[6];
    const float* f1r = (const float*)d_in[7];
    const float* f1i = (const float*)d_in[8];
    const float* f2r = (const float*)d_in[9];
    const float* f2i = (const float*)d_in[10];
    const float* Wfc = (const float*)d_in[11];
    const float* bfc = (const float*)d_in[12];
    const float* mi1 = (const float*)d_in[13];
    const float* mi2 = (const float*)d_in[14];
    const float* mo1 = (const float*)d_in[15];
    const float* mo2 = (const float*)d_in[16];
    const float* aiq = (const float*)d_in[17];
    const float* aik = (const float*)d_in[18];
    const float* aoq = (const float*)d_in[19];
    const float* aok = (const float*)d_in[20];
    float* out = (float*)d_out;

    float *bufA, *bufB, *bufC, *bufD, *bufF, *gate;
    bf16 *Bin, *Bout, *D1B, *C2B;
    cudaGetSymbolAddress((void**)&bufA, g_bufA);
    cudaGetSymbolAddress((void**)&bufB, g_bufB);
    cudaGetSymbolAddress((void**)&bufC, g_bufC);
    cudaGetSymbolAddress((void**)&bufD, g_bufD);
    cudaGetSymbolAddress((void**)&bufF, g_bufF);
    cudaGetSymbolAddress((void**)&gate, g_gate);
    cudaGetSymbolAddress((void**)&Bin,  g_Bin);
    cudaGetSymbolAddress((void**)&Bout, g_Bout);
    cudaGetSymbolAddress((void**)&D1B,  g_D1B);
    cudaGetSymbolAddress((void**)&C2B,  g_C2B);

    constexpr int SMEM_F = 75520;
    cudaFuncSetAttribute(k_gmlpF<false>, cudaFuncAttributeMaxDynamicSharedMemorySize, SMEM_F);
    cudaFuncSetAttribute(k_gmlpF<true >, cudaFuncAttributeMaxDynamicSharedMemorySize, SMEM_F);

    // precompute operator matrices + weight splits
    k_tables<<<(L1*T1 + L2*T2 + 255)/256, 256>>>();
    k_buildM<<<dim3(T1, CC), T1>>>(Lc, Lt);
    k_buildK1<<<(CC*T1 + 255)/256, 256>>>(f1r, f1i);
    k_buildD1<<<dim3(T1, CC), T2>>>(Wfc);
    k_buildK2<<<(CC*T2 + 255)/256, 256>>>(f2r, f2i);
    k_expand2<<<(int)(((size_t)CC*T2*T2 + 255)/256), 256>>>();
    k_splitWF<<<(2*4*192*T1 + 255)/256, 256>>>(mi1, mi2, Bin);
    k_splitW<T2,1><<<(2*1*4*96*T2 + 255)/256, 256>>>(mo1, mo2, Bout);
    k_splitMM<<<(int)(((size_t)CC*2*192*384 + 255)/256), 256>>>();
    k_splitD1<<<(CC*2*96*T1 + 255)/256, 256>>>();
    k_splitC2<<<(CC*2*96*T2 + 255)/256, 256>>>();

    // freq_attn_in: u = Gc^T x, v = Gt^T x ; xc = x + u@Mc[c] + v@Mt[c]
    k_chmix<<<dim3(NN*T1/256, BB), 256>>>(x, Gc, Gt);
    k_mm2MMA<<<dim3(NN/64, CC, BB), 256>>>(bufA, bufB, x, bufC);

    const int NT = BB*CC*NN/64;               // 4096 M-tiles of 64 rows
    const size_t LF1 = (size_t)4*192*T1;      // per-layer stride in g_Bin
    const size_t L2OFF = (size_t)1*4*96*T2;   // per-layer stride in g_Bout

    // input-side layers (512-thread full-N tensor kernel, X read once)
    k_gmlpF<false><<<NT, 512, SMEM_F>>>(bufC, Bin, nullptr, bufA);
    k_gate<T1><<<BB, T1>>>(aiq, aik);
    k_gmlpF<true ><<<NT, 512, SMEM_F>>>(bufA, Bin + LF1, gate, bufC);
    k_gate<T1><<<BB, T1>>>(aiq + CC*EE, aik + CC*EE);

    // h_y = (x + xc*(1+g)) @ D1[c] + bfc   (fconv1 + fc_idp fused, tensor)
    k_cgemmMMA<T1, true><<<dim3(NN/64, CC, BB), 256>>>(x, bufC, D1B, bfc, gate, bufD);

    // output-side layers (tensor core, n-mean fused)
    k_gmlpMMA<T2,false><<<NT, 256>>>(bufD, Bout, nullptr, bufA);
    k_gate<T2><<<BB, T2>>>(aoq, aok);
    k_gmlpMMA<T2,true ><<<NT, 256>>>(bufA, Bout + L2OFF, gate, bufF);
    k_gate<T2><<<BB, T2>>>(aoq + CC*EE, aok + CC*EE);

    // out = (h_y + y_c*(1+g)) @ C2[c]   (tensor)
    k_cgemmMMA<T2, false><<<dim3(NN/64, CC, BB), 256>>>(bufD, bufF, C2B, nullptr, gate, out);
}

// round 15
// speedup vs baseline: 1.0252x; 1.0252x over previous
#include <cuda_runtime.h>
#include <cuda_bf16.h>
#include <math.h>
#include <stdint.h>

#define BB 16
#define CC 32
#define NN 512
#define T1 192
#define T2 96
#define L1 97
#define L2 49
#define EE 64

typedef unsigned long long ull;
typedef __nv_bfloat16 bf16;

static constexpr size_t SZ1 = (size_t)BB*CC*NN*T1;
static constexpr size_t SZ2 = (size_t)BB*CC*NN*T2;

// ---------------- scratch ----------------
__device__ float g_bufA[SZ1];
__device__ float g_bufB[SZ1];
__device__ float g_bufC[SZ1];
__device__ float g_bufD[SZ2];
__device__ float g_bufF[SZ2];
__device__ float g_Mc[CC*T1*T1];
__device__ float g_Mt[CC*T1*T1];
__device__ float g_D1[CC*T1*T2];
__device__ float g_C2[CC*T2*T2];
__device__ float g_cos1[L1*T1];
__device__ float g_sin1[L1*T1];
__device__ float g_cos2[L2*T2];
__device__ float g_sin2[L2*T2];
__device__ float g_K1[CC*T1];
__device__ float g_K2[CC*T2];
__device__ float g_featP[BB*CC*8*T1];
__device__ float g_gate[BB*T1];
// pre-split bf16 weights
__device__ bf16 g_Bin[2*2*4*96*T1];
__device__ bf16 g_Bout[2*1*4*96*T2];
__device__ bf16 g_McB[CC*2*192*384];
__device__ bf16 g_D1B[CC*2*96*T1];
__device__ bf16 g_C2B[CC*2*96*T2];

// ---------------- f32x2 helpers ----------------
__device__ __forceinline__ ull pk2(float lo, float hi) {
    ull r; asm("mov.b64 %0, {%1,%2};" : "=l"(r) : "f"(lo), "f"(hi)); return r;
}
__device__ __forceinline__ void fma2(ull& d, ull a, ull b) {
    asm("fma.rn.f32x2 %0, %1, %2, %0;" : "+l"(d) : "l"(a), "l"(b));
}
__device__ __forceinline__ float2 upk2(ull v) {
    float2 f; asm("mov.b64 {%0,%1}, %2;" : "=f"(f.x), "=f"(f.y) : "l"(v)); return f;
}

__device__ __forceinline__ float gelu_t(float x) {
    float x3 = x*x*x;
    return 0.5f*x*(1.0f + tanhf(0.7978845608028654f*(x + 0.044715f*x3)));
}

__device__ __forceinline__ uint32_t smem_u32(const void* p) {
    uint32_t a;
    asm("{ .reg .u64 t; cvta.to.shared.u64 t, %1; cvt.u32.u64 %0, t; }" : "=r"(a) : "l"(p));
    return a;
}

// ---------------- mma.sync / cp.async helpers ----------------
#define LDM4(r, addr) \
    asm volatile("ldmatrix.sync.aligned.m8n8.x4.shared.b16 {%0,%1,%2,%3}, [%4];" \
        : "=r"((r)[0]), "=r"((r)[1]), "=r"((r)[2]), "=r"((r)[3]) : "r"(addr))

#define MMA_BF16(c, a, b0, b1) \
    asm volatile("mma.sync.aligned.m16n8k16.row.col.f32.bf16.bf16.f32 " \
        "{%0,%1,%2,%3},{%4,%5,%6,%7},{%8,%9},{%0,%1,%2,%3};" \
        : "+f"((c)[0]), "+f"((c)[1]), "+f"((c)[2]), "+f"((c)[3]) \
        : "r"((a)[0]), "r"((a)[1]), "r"((a)[2]), "r"((a)[3]), "r"(b0), "r"(b1))

#define CP16(dst, src) \
    asm volatile("cp.async.cg.shared.global [%0], [%1], 16;" :: "r"(dst), "l"(src))
#define CP_COMMIT() asm volatile("cp.async.commit_group;" ::: "memory")
#define CP_WAIT0()  asm volatile("cp.async.wait_group 0;" ::: "memory")

__device__ __forceinline__ void cvt_hilo_store(float4 v0, float4 v1, bf16* dH, bf16* dL) {
    __nv_bfloat162 h0 = __floats2bfloat162_rn(v0.x, v0.y);
    __nv_bfloat162 h1 = __floats2bfloat162_rn(v0.z, v0.w);
    __nv_bfloat162 h2 = __floats2bfloat162_rn(v1.x, v1.y);
    __nv_bfloat162 h3 = __floats2bfloat162_rn(v1.z, v1.w);
    __nv_bfloat162 l0 = __floats2bfloat162_rn(v0.x - __bfloat162float(h0.x), v0.y - __bfloat162float(h0.y));
    __nv_bfloat162 l1 = __floats2bfloat162_rn(v0.z - __bfloat162float(h1.x), v0.w - __bfloat162float(h1.y));
    __nv_bfloat162 l2 = __floats2bfloat162_rn(v1.x - __bfloat162float(h2.x), v1.y - __bfloat162float(h2.y));
    __nv_bfloat162 l3 = __floats2bfloat162_rn(v1.z - __bfloat162float(h3.x), v1.w - __bfloat162float(h3.y));
    *(uint4*)dH = make_uint4(*(uint32_t*)&h0, *(uint32_t*)&h1, *(uint32_t*)&h2, *(uint32_t*)&h3);
    *(uint4*)dL = make_uint4(*(uint32_t*)&l0, *(uint32_t*)&l1, *(uint32_t*)&l2, *(uint32_t*)&l3);
}

// ---------------- precompute ----------------
__global__ void k_tables() {
    int i = blockIdx.x*blockDim.x + threadIdx.x;
    if (i < L1*T1) {
        int h = i / T1, t = i % T1;
        int m = (h*t) % T1;
        float a = (float)m * (1.0f/96.0f);
        g_cos1[i] = cospif(a);
        g_sin1[i] = sinpif(a);
    }
    int j = i - L1*T1;
    if (j >= 0 && j < L2*T2) {
        int h = j / T2, t = j % T2;
        int m = (h*t) % T2;
        float a = (float)m * (1.0f/48.0f);
        g_cos2[j] = cospif(a);
        g_sin2[j] = sinpif(a);
    }
}

__global__ void k_buildM(const float* __restrict__ Lc, const float* __restrict__ Lt) {
    int t = blockIdx.x, l = blockIdx.y, tp = threadIdx.x;
    float ac = 0.f, as = 0.f;
    for (int h = 0; h < L1; h++) {
        float w = (h == 0 || h == L1-1) ? (1.0f/T1) : (2.0f/T1);
        float lc = Lc[l*L1+h]*w, lt = Lt[l*L1+h]*w;
        ac = fmaf(lc * g_cos1[h*T1+t], g_cos1[h*T1+tp], ac);
        as = fmaf(lt * g_sin1[h*T1+t], g_sin1[h*T1+tp], as);
    }
    size_t o = ((size_t)l*T1 + t)*T1 + tp;
    g_Mc[o] = ac;
    g_Mt[o] = as;
}

__global__ void k_buildK1(const float* __restrict__ Wr, const float* __restrict__ Wi) {
    int i = blockIdx.x*blockDim.x + threadIdx.x;
    if (i >= CC*T1) return;
    int c = i / T1, d = i % T1;
    float acc = 0.f;
    for (int h = 0; h < L1; h++) {
        float w = (h == 0 || h == L1-1) ? (1.0f/T1) : (2.0f/T1);
        acc += w * (Wr[c*L1+h]*g_cos1[h*T1+d] - Wi[c*L1+h]*g_sin1[h*T1+d]);
    }
    g_K1[i] = acc;
}

__global__ void k_buildD1(const float* __restrict__ Wfc) {
    __shared__ float kr[2*T1];
    int t = blockIdx.x, c = blockIdx.y, s2 = threadIdx.x;
    for (int s = s2; s < T1; s += T2) {
        float v = g_K1[c*T1 + s];
        kr[s] = v; kr[s + T1] = v;
    }
    __syncthreads();
    float acc = 0.f;
    const float* kb = kr + (T1 - t);
    for (int s = 0; s < T1; s++)
        acc = fmaf(kb[s], Wfc[s*T2 + s2], acc);
    g_D1[((size_t)c*T1 + t)*T2 + s2] = acc;
}

__global__ void k_buildK2(const float* __restrict__ Wr, const float* __restrict__ Wi) {
    int i = blockIdx.x*blockDim.x + threadIdx.x;
    if (i >= CC*T2) return;
    int c = i / T2, d = i % T2;
    float acc = 0.f;
    for (int h = 0; h < L2; h++) {
        float w = (h == 0 || h == L2-1) ? (1.0f/T2) : (2.0f/T2);
        acc += w * (Wr[c*L2+h]*g_cos2[h*T2+d] - Wi[c*L2+h]*g_sin2[h*T2+d]);
    }
    g_K2[i] = acc;
}
__global__ void k_expand2() {
    size_t i = (size_t)blockIdx.x*blockDim.x + threadIdx.x;
    if (i >= (size_t)CC*T2*T2) return;
    int s = (int)(i % T2);
    int t = (int)((i / T2) % T2);
    int c = (int)(i / ((size_t)T2*T2));
    g_C2[i] = g_K2[c*T2 + ((s - t + T2) % T2)];
}

template<int KTOT, int HALVES>
__global__ void k_splitW(const float* __restrict__ W1, const float* __restrict__ W2,
                         bf16* __restrict__ dst) {
    int total = 2*HALVES*4*96*KTOT;
    int idx = blockIdx.x*blockDim.x + threadIdx.x;
    if (idx >= total) return;
    int k     = idx % KTOT;
    int n     = (idx / KTOT) % 96;
    int mat   = (idx / (KTOT*96)) % 4;
    int half  = (idx / (KTOT*96*4)) % HALVES;
    int layer = idx / (KTOT*96*4*HALVES);
    const float* src = (mat < 2) ? W1 : W2;
    int s = half*96 + n;
    float w = src[(size_t)layer*KTOT*KTOT + (size_t)k*KTOT + s];
    bf16 hi = __float2bfloat16(w);
    bf16 v = (mat & 1) ? __float2bfloat16(w - __bfloat162float(hi)) : hi;
    dst[idx] = v;
}

__global__ void k_splitMM() {
    size_t total = (size_t)CC*2*192*384;
    size_t idx = (size_t)blockIdx.x*blockDim.x + threadIdx.x;
    if (idx >= total) return;
    int k     = (int)(idx % 384);
    int n     = (int)((idx / 384) % 192);
    int plane = (int)((idx / (384*192)) % 2);
    int c     = (int)(idx / (384*192*2));
    float w = (k < 192) ? g_Mc[((size_t)c*T1 + k)*T1 + n]
                        : g_Mt[((size_t)c*T1 + (k-192))*T1 + n];
    bf16 hi = __float2bfloat16(w);
    g_McB[idx] = plane ? __float2bfloat16(w - __bfloat162float(hi)) : hi;
}

__global__ void k_splitD1() {
    int total = CC*2*96*T1;
    int idx = blockIdx.x*blockDim.x + threadIdx.x;
    if (idx >= total) return;
    int k     = idx % T1;
    int n     = (idx / T1) % 96;
    int plane = (idx / (T1*96)) % 2;
    int c     = idx / (T1*96*2);
    float w = g_D1[((size_t)c*T1 + k)*T2 + n];
    bf16 hi = __float2bfloat16(w);
    g_D1B[idx] = plane ? __float2bfloat16(w - __bfloat162float(hi)) : hi;
}

__global__ void k_splitC2() {
    int total = CC*2*96*T2;
    int idx = blockIdx.x*blockDim.x + threadIdx.x;
    if (idx >= total) return;
    int k     = idx % T2;
    int n     = (idx / T2) % 96;
    int plane = (idx / (T2*96)) % 2;
    int c     = idx / (T2*96*2);
    float w = g_C2[((size_t)c*T2 + k)*T2 + n];
    bf16 hi = __float2bfloat16(w);
    g_C2B[idx] = plane ? __float2bfloat16(w - __bfloat162float(hi)) : hi;
}

// ---------------- channel mix ----------------
__global__ void __launch_bounds__(256) k_chmix(const float* __restrict__ x,
                                               const float* __restrict__ Gc,
                                               const float* __restrict__ Gt) {
    __shared__ __align__(16) float2 sG[CC*CC];
    int tid = threadIdx.x;
    for (int i = tid; i < CC*CC; i += 256) sG[i] = make_float2(Gc[i], Gt[i]);
    __syncthreads();
    int b = blockIdx.y;
    size_t m = (size_t)blockIdx.x*256 + tid;
    ull a[CC];
#pragma unroll
    for (int l = 0; l < CC; l++) a[l] = 0ull;
    for (int c = 0; c < CC; c++) {
        float xv = x[((size_t)(b*CC + c)*NN)*T1 + m];
        ull xp = pk2(xv, xv);
#pragma unroll
        for (int l = 0; l < CC; l++) fma2(a[l], xp, *(const ull*)&sG[c*CC + l]);
    }
#pragma unroll
    for (int l = 0; l < CC; l++) {
        float2 p = upk2(a[l]);
        g_bufA[((size_t)(b*CC + l)*NN)*T1 + m] = p.x;
        g_bufB[((size_t)(b*CC + l)*NN)*T1 + m] = p.y;
    }
}

// ---------------- mm2 (tensor, merged N=192): Y = resid + [u|v] @ [Mc;Mt][c] ----------------
__global__ void __launch_bounds__(256) k_mm2MMA(const float* __restrict__ U,
                                                const float* __restrict__ V,
                                                const float* __restrict__ resid,
                                                float* __restrict__ Y) {
    constexpr int AST = 40;
    __shared__ __align__(16) bf16 sAh[64*AST];
    __shared__ __align__(16) bf16 sAl[64*AST];
    __shared__ __align__(16) bf16 sB[2*192*AST];
    int tid = threadIdx.x, lane = tid & 31, wid = tid >> 5;
    int wm = wid & 3, wn = wid >> 2;
    int c = blockIdx.y, b = blockIdx.z;
    size_t row0 = (size_t)(b*CC + c)*NN + (size_t)blockIdx.x*64;
    const bf16* Wc = g_McB + (size_t)c*2*192*384;

    float cc[12][4];
#pragma unroll
    for (int i = 0; i < 12; i++)
#pragma unroll
        for (int j = 0; j < 4; j++) cc[i][j] = 0.f;

    uint32_t aOff = (uint32_t)((wm*16 + (lane & 15))*AST + ((lane >> 4) << 3)) * 2;
    uint32_t aAddrH = smem_u32(sAh) + aOff;
    uint32_t aAddrL = smem_u32(sAl) + aOff;
    uint32_t bRow = (uint32_t)((lane & 7) + ((lane >> 4) << 3));
    uint32_t bOff = (bRow*AST + (((lane >> 3) & 1) << 3)) * 2;
    uint32_t sBbase = smem_u32(sB);

    int arow = tid >> 2, akg = (tid & 3) * 8;
    bf16* aDstH = &sAh[arow*AST + akg];
    bf16* aDstL = &sAl[arow*AST + akg];

    float4 nx0, nx1;
    uint4 nB[6];
    {
        const float* xr = U + (row0 + arow)*T1 + akg;
        nx0 = *(const float4*)xr; nx1 = *(const float4*)(xr + 4);
#pragma unroll
        for (int it = 0; it < 6; it++) {
            int i = tid + it*256;
            int plane = i / 768, rem = i % 768;
            int n = rem >> 2, kg = (rem & 3) * 8;
            nB[it] = *(const uint4*)&Wc[((size_t)plane*192 + n)*384 + kg];
        }
    }
    for (int kc = 0; kc < 12; kc++) {
        cvt_hilo_store(nx0, nx1, aDstH, aDstL);
#pragma unroll
        for (int it = 0; it < 6; it++) {
            int i = tid + it*256;
            int plane = i / 768, rem = i % 768;
            int n = rem >> 2, kg = (rem & 3) * 8;
            *(uint4*)&sB[(plane*192 + n)*AST + kg] = nB[it];
        }
        __syncthreads();
        if (kc + 1 < 12) {
            int kn = kc + 1;
            const float* Xs = (kn < 6) ? U : V;
            int kl = (kn < 6) ? kn : kn - 6;
            const float* xr = Xs + (row0 + arow)*T1 + kl*32 + akg;
            nx0 = *(const float4*)xr; nx1 = *(const float4*)(xr + 4);
#pragma unroll
            for (int it = 0; it < 6; it++) {
                int i = tid + it*256;
                int plane = i / 768, rem = i % 768;
                int n = rem >> 2, kg = (rem & 3) * 8;
                nB[it] = *(const uint4*)&Wc[((size_t)plane*192 + n)*384 + kn*32 + kg];
            }
        }
#pragma unroll
        for (int k16 = 0; k16 < 2; k16++) {
            uint32_t kof = (uint32_t)(k16 * 32);
            uint32_t ah[4], al[4];
            LDM4(ah, aAddrH + kof);
            LDM4(al, aAddrL + kof);
            uint32_t baseH = sBbase + bOff + kof;
            uint32_t baseL = baseH + (uint32_t)(192*AST)*2;
#pragma unroll
            for (int pr = 0; pr < 6; pr++) {
                uint32_t po = (uint32_t)((wn*96 + pr*16)*AST)*2;
                uint32_t bh[4], bl[4];
                LDM4(bh, baseH + po);
                LDM4(bl, baseL + po);
                MMA_BF16(cc[2*pr],   ah, bh[0], bh[1]);
                MMA_BF16(cc[2*pr+1], ah, bh[2], bh[3]);
                MMA_BF16(cc[2*pr],   al, bh[0], bh[1]);
                MMA_BF16(cc[2*pr+1], al, bh[2], bh[3]);
                MMA_BF16(cc[2*pr],   ah, bl[0], bl[1]);
                MMA_BF16(cc[2*pr+1], ah, bl[2], bl[3]);
            }
        }
        __syncthreads();
    }

    int g = lane >> 2, tg = lane & 3;
    size_t mrow = row0 + (size_t)wm*16 + g;
    int colb = wn*96 + tg*2;
#pragma unroll
    for (int nf = 0; nf < 12; nf++) {
        int col = colb + nf*8;
        float2 r0 = *(const float2*)&resid[mrow*T1 + col];
        float2 r1 = *(const float2*)&resid[(mrow + 8)*T1 + col];
        *(float2*)&Y[mrow*T1 + col]       = make_float2(cc[nf][0] + r0.x, cc[nf][1] + r0.y);
        *(float2*)&Y[(mrow + 8)*T1 + col] = make_float2(cc[nf][2] + r1.x, cc[nf][3] + r1.y);
    }
}

// ---------------- channel GEMM (tensor): Y = (X1 + sg*X2) @ W[c] [+bias] ----------------
template<int KTOT, bool BIAS>
__global__ void __launch_bounds__(256) k_cgemmMMA(const float* __restrict__ X1,
                                                  const float* __restrict__ X2,
                                                  const bf16* __restrict__ WB,
                                                  const float* __restrict__ bias,
                                                  const float* __restrict__ gate,
                                                  float* __restrict__ Y) {
    constexpr int AST = 40, KC = KTOT/32;
    __shared__ __align__(16) bf16 sAh[64*AST];
    __shared__ __align__(16) bf16 sAl[64*AST];
    __shared__ __align__(16) bf16 sB[2*96*AST];
    __shared__ float sg[KTOT];
    int tid = threadIdx.x, lane = tid & 31, wid = tid >> 5;
    int wm = wid & 3, wn = wid >> 2;
    int c = blockIdx.y, b = blockIdx.z;
    size_t row0 = (size_t)(b*CC + c)*NN + (size_t)blockIdx.x*64;
    const bf16* Wc = WB + (size_t)c*2*96*KTOT;

    for (int t = tid; t < KTOT; t += 256) sg[t] = 1.0f + gate[b*KTOT + t];
    __syncthreads();

    float cc[6][4];
#pragma unroll
    for (int i = 0; i < 6; i++)
#pragma unroll
        for (int j = 0; j < 4; j++) cc[i][j] = 0.f;

    uint32_t aOff = (uint32_t)((wm*16 + (lane & 15))*AST + ((lane >> 4) << 3)) * 2;
    uint32_t aAddrH = smem_u32(sAh) + aOff;
    uint32_t aAddrL = smem_u32(sAl) + aOff;
    uint32_t bRow = (uint32_t)(wn*48 + (lane & 7) + ((lane >> 4) << 3));
    uint32_t bOff = (bRow*AST + (((lane >> 3) & 1) << 3)) * 2;
    uint32_t sBbase = smem_u32(sB);

    int arow = tid >> 2, akg = (tid & 3) * 8;
    const float* x1r = X1 + (row0 + arow)*KTOT;
    const float* x2r = X2 + (row0 + arow)*KTOT;
    bf16* aDstH = &sAh[arow*AST + akg];
    bf16* aDstL = &sAl[arow*AST + akg];

    float4 na0, na1, nb0, nb1;
    uint4 nB[3];
    {
        na0 = *(const float4*)&x1r[akg];
        na1 = *(const float4*)&x1r[akg + 4];
        nb0 = *(const float4*)&x2r[akg];
        nb1 = *(const float4*)&x2r[akg + 4];
#pragma unroll
        for (int it = 0; it < 3; it++) {
            int i = tid + it*256;
            int plane = i / 384, rem = i % 384;
            int n = rem >> 2, kg = (rem & 3) * 8;
            nB[it] = *(const uint4*)&Wc[((size_t)plane*96 + n)*KTOT + kg];
        }
    }
    for (int kc = 0; kc < KC; kc++) {
        {
            int k0 = kc*32 + akg;
            float4 v0 = na0, v1 = na1;
            v0.x = fmaf(nb0.x, sg[k0],   v0.x);
            v0.y = fmaf(nb0.y, sg[k0+1], v0.y);
            v0.z = fmaf(nb0.z, sg[k0+2], v0.z);
            v0.w = fmaf(nb0.w, sg[k0+3], v0.w);
            v1.x = fmaf(nb1.x, sg[k0+4], v1.x);
            v1.y = fmaf(nb1.y, sg[k0+5], v1.y);
            v1.z = fmaf(nb1.z, sg[k0+6], v1.z);
            v1.w = fmaf(nb1.w, sg[k0+7], v1.w);
            cvt_hilo_store(v0, v1, aDstH, aDstL);
#pragma unroll
            for (int it = 0; it < 3; it++) {
                int i = tid + it*256;
                int plane = i / 384, rem = i % 384;
                int n = rem >> 2, kg = (rem & 3) * 8;
                *(uint4*)&sB[(plane*96 + n)*AST + kg] = nB[it];
            }
        }
        __syncthreads();
        if (kc + 1 < KC) {
            int kn = (kc + 1)*32 + akg;
            na0 = *(const float4*)&x1r[kn];
            na1 = *(const float4*)&x1r[kn + 4];
            nb0 = *(const float4*)&x2r[kn];
            nb1 = *(const float4*)&x2r[kn + 4];
#pragma unroll
            for (int it = 0; it < 3; it++) {
                int i = tid + it*256;
                int plane = i / 384, rem = i % 384;
                int n = rem >> 2, kg = (rem & 3) * 8;
                nB[it] = *(const uint4*)&Wc[((size_t)plane*96 + n)*KTOT + (kc+1)*32 + kg];
            }
        }
#pragma unroll
        for (int k16 = 0; k16 < 2; k16++) {
            uint32_t kof = (uint32_t)(k16 * 32);
            uint32_t ah[4], al[4];
            LDM4(ah, aAddrH + kof);
            LDM4(al, aAddrL + kof);
            uint32_t baseH = sBbase + bOff + kof;
            uint32_t baseL = baseH + (uint32_t)(96*AST)*2;
#pragma unroll
            for (int pr = 0; pr < 3; pr++) {
                uint32_t po = (uint32_t)(pr*16*AST)*2;
                uint32_t bh[4], bl[4];
                LDM4(bh, baseH + po);
                LDM4(bl, baseL + po);
                MMA_BF16(cc[2*pr],   ah, bh[0], bh[1]);
                MMA_BF16(cc[2*pr+1], ah, bh[2], bh[3]);
                MMA_BF16(cc[2*pr],   al, bh[0], bh[1]);
                MMA_BF16(cc[2*pr+1], al, bh[2], bh[3]);
                MMA_BF16(cc[2*pr],   ah, bl[0], bl[1]);
                MMA_BF16(cc[2*pr+1], ah, bl[2], bl[3]);
            }
        }
        __syncthreads();
    }

    int g = lane >> 2, tg = lane & 3;
    size_t mrow = row0 + (size_t)wm*16 + g;
    int colb = wn*48 + tg*2;
#pragma unroll
    for (int nf = 0; nf < 6; nf++) {
        int col = colb + nf*8;
        float2 o0 = make_float2(cc[nf][0], cc[nf][1]);
        float2 o1 = make_float2(cc[nf][2], cc[nf][3]);
        if (BIAS) {
            float2 bv = *(const float2*)&bias[col];
            o0.x += bv.x; o0.y += bv.y; o1.x += bv.x; o1.y += bv.y;
        }
        *(float2*)&Y[mrow*96 + col]       = o0;
        *(float2*)&Y[(mrow + 8)*96 + col] = o1;
    }
}

// ---------------- tensor gmlp: cp.async double-buffered pipeline, 1 sync/chunk ----------------
// dyn smem layout: sA [2 buf][hi 5120 | lo 5120] @0 (20480), sB [2 buf][30720] @20480 (61440),
//                  sg @81920 (<=768), sFP @82688 (1536)  => 84224
template<int KTOT, bool G1>
__global__ void __launch_bounds__(256) k_gmlpMMA(const float* __restrict__ X,
                                                 const bf16* __restrict__ Bw,
                                                 const float* __restrict__ gate,
                                                 float* __restrict__ Y) {
    constexpr int KC = KTOT/32;
    constexpr int AST = 40;
    constexpr uint32_t ABUF = 10240, BBUF = 30720;
    extern __shared__ char sm[];
    bf16* sA = (bf16*)sm;                      // buf*ABUF: hi @+0, lo @+5120
    char* sBc = sm + 20480;
    float* sg = (float*)(sm + 81920);
    float (*sFP)[48] = (float(*)[48])(sm + 82688);
    int tid = threadIdx.x, lane = tid & 31, wid = tid >> 5;
    int wm = wid & 3, wn = wid >> 2;
    int half = blockIdx.y;
    int tix = blockIdx.x;
    size_t row0 = (size_t)tix * 64;
    int b = tix >> 8;
    int ch = (tix >> 3) & 31;
    int tile = tix & 7;
    const bf16* BwH = Bw + (size_t)half * 4*96*KTOT;

    if (G1) {
        for (int t = tid; t < KTOT; t += 256) sg[t] = 1.0f + gate[b*KTOT + t];
        __syncthreads();   // sg visible before first A convert
    }

    float c1[6][4], c2[6][4];
#pragma unroll
    for (int i = 0; i < 6; i++)
#pragma unroll
        for (int j = 0; j < 4; j++) { c1[i][j] = 0.f; c2[i][j] = 0.f; }

    uint32_t sAbase = smem_u32(sA);
    uint32_t sBbase = smem_u32(sBc);
    uint32_t aOff = (uint32_t)((wm*16 + (lane & 15))*AST + ((lane >> 4) << 3)) * 2;
    uint32_t bRow = (uint32_t)(wn*48 + (lane & 7) + ((lane >> 4) << 3));
    uint32_t bOff = (bRow*AST + (((lane >> 3) & 1) << 3)) * 2;

    int arow = tid >> 2, akg = (tid & 3) * 8;
    const float* xrow = X + (row0 + arow)*KTOT;
    uint32_t aDstOff = (uint32_t)(arow*AST + akg) * 2;   // byte offset within buffer (hi)

    // per-thread B copy descriptors (6 x 16B)
    uint32_t bDst[6];
    const bf16* bSrc[6];
#pragma unroll
    for (int it = 0; it < 6; it++) {
        int i = tid + it*256;
        int mat = i / 384, rem = i % 384;
        int n = rem >> 2, kg = (rem & 3) * 8;
        bDst[it] = (uint32_t)((mat*96 + n)*AST + kg) * 2;
        bSrc[it] = &BwH[((size_t)mat*96 + n)*KTOT + kg];
    }

    // prologue: stage chunk 0 into buffer 0
    {
        float4 v0 = *(const float4*)&xrow[0];
        float4 v1 = *(const float4*)&xrow[4 + (akg & ~7)];   // placeholder, fixed below
        // correct loads:
        v0 = *(const float4*)&xrow[akg];
        v1 = *(const float4*)&xrow[akg + 4];
        if (G1) {
            v0.x *= sg[akg];   v0.y *= sg[akg+1]; v0.z *= sg[akg+2]; v0.w *= sg[akg+3];
            v1.x *= sg[akg+4]; v1.y *= sg[akg+5]; v1.z *= sg[akg+6]; v1.w *= sg[akg+7];
        }
        cvt_hilo_store(v0, v1, (bf16*)(sm + aDstOff), (bf16*)(sm + 5120 + aDstOff));
#pragma unroll
        for (int it = 0; it < 6; it++) CP16(sBbase + bDst[it], bSrc[it]);
        CP_COMMIT();
    }

    for (int kc = 0; kc < KC; kc++) {
        uint32_t buf = (uint32_t)(kc & 1);
        // prefetch x regs for next chunk (global load, no hazard)
        float4 v0, v1;
        if (kc + 1 < KC) {
            int kn = (kc + 1)*32;
            v0 = *(const float4*)&xrow[kn + akg];
            v1 = *(const float4*)&xrow[kn + akg + 4];
        }
        CP_WAIT0();          // B(kc) arrived
        __syncthreads();     // A(kc) stores visible; all threads done reading buf^1 (chunk kc-1)
        if (kc + 1 < KC) {
            uint32_t nb = buf ^ 1;
            int k0 = (kc + 1)*32 + akg;
            if (G1) {
                v0.x *= sg[k0];   v0.y *= sg[k0+1]; v0.z *= sg[k0+2]; v0.w *= sg[k0+3];
                v1.x *= sg[k0+4]; v1.y *= sg[k0+5]; v1.z *= sg[k0+6]; v1.w *= sg[k0+7];
            }
            cvt_hilo_store(v0, v1,
                           (bf16*)(sm + nb*ABUF + aDstOff),
                           (bf16*)(sm + nb*ABUF + 5120 + aDstOff));
#pragma unroll
            for (int it = 0; it < 6; it++)
                CP16(sBbase + nb*BBUF + bDst[it], bSrc[it] + (kc + 1)*32);
            CP_COMMIT();
        }
        // compute chunk kc from buf
        uint32_t aAddrH = sAbase + buf*ABUF + aOff;
        uint32_t aAddrL = aAddrH + 5120;
        uint32_t sBcur = sBbase + buf*BBUF;
#pragma unroll
        for (int k16 = 0; k16 < 2; k16++) {
            uint32_t kof = (uint32_t)(k16 * 32);
            uint32_t ah[4], al[4];
            LDM4(ah, aAddrH + kof);
            LDM4(al, aAddrL + kof);
#pragma unroll
            for (int mat = 0; mat < 2; mat++) {
                float (*cf)[4] = mat ? c2 : c1;
                uint32_t baseH = sBcur + (uint32_t)((mat*2 + 0)*96*AST)*2 + bOff + kof;
                uint32_t baseL = sBcur + (uint32_t)((mat*2 + 1)*96*AST)*2 + bOff + kof;
#pragma unroll
                for (int pr = 0; pr < 3; pr++) {
                    uint32_t po = (uint32_t)(pr*16*AST)*2;
                    uint32_t bh[4], bl[4];
                    LDM4(bh, baseH + po);
                    LDM4(bl, baseL + po);
                    MMA_BF16(cf[2*pr],   ah, bh[0], bh[1]);
                    MMA_BF16(cf[2*pr+1], ah, bh[2], bh[3]);
                    MMA_BF16(cf[2*pr],   al, bh[0], bh[1]);
                    MMA_BF16(cf[2*pr+1], al, bh[2], bh[3]);
                    MMA_BF16(cf[2*pr],   ah, bl[0], bl[1]);
                    MMA_BF16(cf[2*pr+1], ah, bl[2], bl[3]);
                }
            }
        }
    }

    // epilogue: o = (X@W1)*gelu(X@W2), store + column partial sums
    __syncthreads();
    int g = lane >> 2, tg = lane & 3;
    size_t mrow = row0 + (size_t)wm*16 + g;
    int colb = half*96 + wn*48 + tg*2;
    float colsum[12];
#pragma unroll
    for (int nf = 0; nf < 6; nf++) {
        int col = colb + nf*8;
        float2 o0 = make_float2(c1[nf][0]*gelu_t(c2[nf][0]), c1[nf][1]*gelu_t(c2[nf][1]));
        float2 o1 = make_float2(c1[nf][2]*gelu_t(c2[nf][2]), c1[nf][3]*gelu_t(c2[nf][3]));
        *(float2*)&Y[mrow*KTOT + col] = o0;
        *(float2*)&Y[(mrow + 8)*KTOT + col] = o1;
        colsum[2*nf]   = o0.x + o1.x;
        colsum[2*nf+1] = o0.y + o1.y;
    }
#pragma unroll
    for (int i = 0; i < 12; i++) {
        float v = colsum[i];
        v += __shfl_xor_sync(0xFFFFFFFF, v, 16);
        v += __shfl_xor_sync(0xFFFFFFFF, v, 8);
        v += __shfl_xor_sync(0xFFFFFFFF, v, 4);
        colsum[i] = v;
    }
    if (lane < 4) {
#pragma unroll
        for (int nf = 0; nf < 6; nf++) {
            sFP[wid][lane*2 + nf*8]     = colsum[2*nf];
            sFP[wid][lane*2 + nf*8 + 1] = colsum[2*nf+1];
        }
    }
    __syncthreads();
    if (tid < 96) {
        int wn2 = tid / 48, idx = tid % 48;
        float tot = sFP[wn2*4+0][idx] + sFP[wn2*4+1][idx] + sFP[wn2*4+2][idx] + sFP[wn2*4+3][idx];
        g_featP[((size_t)(b*CC + ch)*8 + tile)*KTOT + half*96 + wn2*48 + idx] = tot;
    }
}

// ---------------- attn gate (reads featP partials, 8 tiles) ----------------
template<int T>
__global__ void __launch_bounds__(T) k_gate(const float* __restrict__ Wq,
                                            const float* __restrict__ Wk) {
    __shared__ float ks[T][EE];
    int b = blockIdx.x, t = threadIdx.x;
    float q[EE], kk[EE];
#pragma unroll
    for (int e = 0; e < EE; e++) { q[e] = 0.f; kk[e] = 0.f; }
    for (int c = 0; c < CC; c++) {
        float f = 0.f;
#pragma unroll
        for (int p = 0; p < 8; p++) f += g_featP[((size_t)(b*CC + c)*8 + p)*T + t];
        f *= (1.0f/NN);
#pragma unroll
        for (int e = 0; e < EE; e++) {
            q[e]  = fmaf(f, Wq[c*EE + e], q[e]);
            kk[e] = fmaf(f, Wk[c*EE + e], kk[e]);
        }
    }
#pragma unroll
    for (int e = 0; e < EE; e++) ks[t][e] = kk[e];
    __syncthreads();
    float smax = -1e30f, stt = 0.f;
    for (int j = 0; j < T; j++) {
        float d = 0.f;
#pragma unroll
        for (int e = 0; e < EE; e++) d = fmaf(q[e], ks[j][e], d);
        d *= 0.125f;
        if (j == t) stt = d;
        smax = fmaxf(smax, d);
    }
    float ssum = 0.f;
    for (int j = 0; j < T; j++) {
        float d = 0.f;
#pragma unroll
        for (int e = 0; e < EE; e++) d = fmaf(q[e], ks[j][e], d);
        ssum += expf(d*0.125f - smax);
    }
    float p = expf(stt - smax) / ssum;
    g_gate[b*T + t] = gelu_t(p);
}

// ---------------- driver ----------------
extern "C" void kernel_launch(void* const* d_in, const int* in_sizes, int n_in,
                              void* d_out, int out_size) {
    const float* x   = (const float*)d_in[0];
    const float* Gc  = (const float*)d_in[3];
    const float* Lc  = (const float*)d_in[4];
    const float* Gt  = (const float*)d_in[5];
    const float* Lt  = (const float*)d_in[6];
    const float* f1r = (const float*)d_in[7];
    const float* f1i = (const float*)d_in[8];
    const float* f2r = (const float*)d_in[9];
    const float* f2i = (const float*)d_in[10];
    const float* Wfc = (const float*)d_in[11];
    const float* bfc = (const float*)d_in[12];
    const float* mi1 = (const float*)d_in[13];
    const float* mi2 = (const float*)d_in[14];
    const float* mo1 = (const float*)d_in[15];
    const float* mo2 = (const float*)d_in[16];
    const float* aiq = (const float*)d_in[17];
    const float* aik = (const float*)d_in[18];
    const float* aoq = (const float*)d_in[19];
    const float* aok = (const float*)d_in[20];
    float* out = (float*)d_out;

    float *bufA, *bufB, *bufC, *bufD, *bufF, *gate;
    bf16 *Bin, *Bout, *D1B, *C2B;
    cudaGetSymbolAddress((void**)&bufA, g_bufA);
    cudaGetSymbolAddress((void**)&bufB, g_bufB);
    cudaGetSymbolAddress((void**)&bufC, g_bufC);
    cudaGetSymbolAddress((void**)&bufD, g_bufD);
    cudaGetSymbolAddress((void**)&bufF, g_bufF);
    cudaGetSymbolAddress((void**)&gate, g_gate);
    cudaGetSymbolAddress((void**)&Bin,  g_Bin);
    cudaGetSymbolAddress((void**)&Bout, g_Bout);
    cudaGetSymbolAddress((void**)&D1B,  g_D1B);
    cudaGetSymbolAddress((void**)&C2B,  g_C2B);

    constexpr int SMEM_G = 84224;
    cudaFuncSetAttribute(k_gmlpMMA<T1,false>, cudaFuncAttributeMaxDynamicSharedMemorySize, SMEM_G);
    cudaFuncSetAttribute(k_gmlpMMA<T1,true >, cudaFuncAttributeMaxDynamicSharedMemorySize, SMEM_G);
    cudaFuncSetAttribute(k_gmlpMMA<T2,false>, cudaFuncAttributeMaxDynamicSharedMemorySize, SMEM_G);
    cudaFuncSetAttribute(k_gmlpMMA<T2,true >, cudaFuncAttributeMaxDynamicSharedMemorySize, SMEM_G);

    // precompute operator matrices + weight splits
    k_tables<<<(L1*T1 + L2*T2 + 255)/256, 256>>>();
    k_buildM<<<dim3(T1, CC), T1>>>(Lc, Lt);
    k_buildK1<<<(CC*T1 + 255)/256, 256>>>(f1r, f1i);
    k_buildD1<<<dim3(T1, CC), T2>>>(Wfc);
    k_buildK2<<<(CC*T2 + 255)/256, 256>>>(f2r, f2i);
    k_expand2<<<(int)(((size_t)CC*T2*T2 + 255)/256), 256>>>();
    k_splitW<T1,2><<<(2*2*4*96*T1 + 255)/256, 256>>>(mi1, mi2, Bin);
    k_splitW<T2,1><<<(2*1*4*96*T2 + 255)/256, 256>>>(mo1, mo2, Bout);
    k_splitMM<<<(int)(((size_t)CC*2*192*384 + 255)/256), 256>>>();
    k_splitD1<<<(CC*2*96*T1 + 255)/256, 256>>>();
    k_splitC2<<<(CC*2*96*T2 + 255)/256, 256>>>();

    // freq_attn_in: u = Gc^T x, v = Gt^T x ; xc = x + u@Mc[c] + v@Mt[c]
    k_chmix<<<dim3(NN*T1/256, BB), 256>>>(x, Gc, Gt);
    k_mm2MMA<<<dim3(NN/64, CC, BB), 256>>>(bufA, bufB, x, bufC);

    const int NT = BB*CC*NN/64;               // 4096 M-tiles of 64 rows
    const size_t L1OFF = (size_t)2*4*96*T1;
    const size_t L2OFF = (size_t)1*4*96*T2;

    // input-side layers (tensor core, cp.async pipeline, n-mean fused)
    k_gmlpMMA<T1,false><<<dim3(NT, 2), 256, SMEM_G>>>(bufC, Bin, nullptr, bufA);
    k_gate<T1><<<BB, T1>>>(aiq, aik);
    k_gmlpMMA<T1,true ><<<dim3(NT, 2), 256, SMEM_G>>>(bufA, Bin + L1OFF, gate, bufC);
    k_gate<T1><<<BB, T1>>>(aiq + CC*EE, aik + CC*EE);

    // h_y = (x + xc*(1+g)) @ D1[c] + bfc   (fconv1 + fc_idp fused, tensor)
    k_cgemmMMA<T1, true><<<dim3(NN/64, CC, BB), 256>>>(x, bufC, D1B, bfc, gate, bufD);

    // output-side layers (tensor core, cp.async pipeline, n-mean fused)
    k_gmlpMMA<T2,false><<<dim3(NT, 1), 256, SMEM_G>>>(bufD, Bout, nullptr, bufA);
    k_gate<T2><<<BB, T2>>>(aoq, aok);
    k_gmlpMMA<T2,true ><<<dim3(NT, 1), 256, SMEM_G>>>(bufA, Bout + L2OFF, gate, bufF);
    k_gate<T2><<<BB, T2>>>(aoq + CC*EE, aik == aok ? aok : aok + CC*EE);   // layer-1 weights
    // (the expression above always evaluates to aok + CC*EE; kept simple:)

    // out = (h_y + y_c*(1+g)) @ C2[c]   (tensor)
    k_cgemmMMA<T2, false><<<dim3(NN/64, CC, BB), 256>>>(bufD, bufF, C2B, nullptr, gate, out);
}

// round 16
// speedup vs baseline: 1.0637x; 1.0376x over previous
#include <cuda_runtime.h>
#include <cuda_bf16.h>
#include <math.h>
#include <stdint.h>

#define BB 16
#define CC 32
#define NN 512
#define T1 192
#define T2 96
#define L1 97
#define L2 49
#define EE 64

typedef unsigned long long ull;
typedef __nv_bfloat16 bf16;

static constexpr size_t SZ1 = (size_t)BB*CC*NN*T1;
static constexpr size_t SZ2 = (size_t)BB*CC*NN*T2;

// ---------------- scratch ----------------
__device__ float g_bufA[SZ1];
__device__ float g_bufB[SZ1];
__device__ float g_bufC[SZ1];
__device__ float g_bufD[SZ2];
__device__ float g_bufF[SZ2];
__device__ float g_Mc[CC*T1*T1];
__device__ float g_Mt[CC*T1*T1];
__device__ float g_D1[CC*T1*T2];
__device__ float g_C2[CC*T2*T2];
__device__ float g_cos1[L1*T1];
__device__ float g_sin1[L1*T1];
__device__ float g_cos2[L2*T2];
__device__ float g_sin2[L2*T2];
__device__ float g_K1[CC*T1];
__device__ float g_K2[CC*T2];
__device__ float g_featP[BB*CC*8*T1];
__device__ float g_gate[BB*T1];
// pre-split bf16 weights
__device__ bf16 g_Bin[2*2*4*96*T1];
__device__ bf16 g_Bout[2*1*4*96*T2];
__device__ bf16 g_McB[CC*2*192*384];
__device__ bf16 g_D1B[CC*2*96*T1];
__device__ bf16 g_C2B[CC*2*96*T2];

// ---------------- f32x2 helpers ----------------
__device__ __forceinline__ ull pk2(float lo, float hi) {
    ull r; asm("mov.b64 %0, {%1,%2};" : "=l"(r) : "f"(lo), "f"(hi)); return r;
}
__device__ __forceinline__ void fma2(ull& d, ull a, ull b) {
    asm("fma.rn.f32x2 %0, %1, %2, %0;" : "+l"(d) : "l"(a), "l"(b));
}
__device__ __forceinline__ float2 upk2(ull v) {
    float2 f; asm("mov.b64 {%0,%1}, %2;" : "=f"(f.x), "=f"(f.y) : "l"(v)); return f;
}

__device__ __forceinline__ float gelu_t(float x) {
    float x3 = x*x*x;
    return 0.5f*x*(1.0f + tanhf(0.7978845608028654f*(x + 0.044715f*x3)));
}

__device__ __forceinline__ uint32_t smem_u32(const void* p) {
    uint32_t a;
    asm("{ .reg .u64 t; cvta.to.shared.u64 t, %1; cvt.u32.u64 %0, t; }" : "=r"(a) : "l"(p));
    return a;
}

// ---------------- mma.sync / cp.async helpers ----------------
#define LDM4(r, addr) \
    asm volatile("ldmatrix.sync.aligned.m8n8.x4.shared.b16 {%0,%1,%2,%3}, [%4];" \
        : "=r"((r)[0]), "=r"((r)[1]), "=r"((r)[2]), "=r"((r)[3]) : "r"(addr))

#define MMA_BF16(c, a, b0, b1) \
    asm volatile("mma.sync.aligned.m16n8k16.row.col.f32.bf16.bf16.f32 " \
        "{%0,%1,%2,%3},{%4,%5,%6,%7},{%8,%9},{%0,%1,%2,%3};" \
        : "+f"((c)[0]), "+f"((c)[1]), "+f"((c)[2]), "+f"((c)[3]) \
        : "r"((a)[0]), "r"((a)[1]), "r"((a)[2]), "r"((a)[3]), "r"(b0), "r"(b1))

#define CP16(dst, src) \
    asm volatile("cp.async.cg.shared.global [%0], [%1], 16;" :: "r"(dst), "l"(src))
#define CP_COMMIT() asm volatile("cp.async.commit_group;" ::: "memory")
#define CP_WAIT0()  asm volatile("cp.async.wait_group 0;" ::: "memory")

__device__ __forceinline__ void cvt_hilo_store(float4 v0, float4 v1, bf16* dH, bf16* dL) {
    __nv_bfloat162 h0 = __floats2bfloat162_rn(v0.x, v0.y);
    __nv_bfloat162 h1 = __floats2bfloat162_rn(v0.z, v0.w);
    __nv_bfloat162 h2 = __floats2bfloat162_rn(v1.x, v1.y);
    __nv_bfloat162 h3 = __floats2bfloat162_rn(v1.z, v1.w);
    __nv_bfloat162 l0 = __floats2bfloat162_rn(v0.x - __bfloat162float(h0.x), v0.y - __bfloat162float(h0.y));
    __nv_bfloat162 l1 = __floats2bfloat162_rn(v0.z - __bfloat162float(h1.x), v0.w - __bfloat162float(h1.y));
    __nv_bfloat162 l2 = __floats2bfloat162_rn(v1.x - __bfloat162float(h2.x), v1.y - __bfloat162float(h2.y));
    __nv_bfloat162 l3 = __floats2bfloat162_rn(v1.z - __bfloat162float(h3.x), v1.w - __bfloat162float(h3.y));
    *(uint4*)dH = make_uint4(*(uint32_t*)&h0, *(uint32_t*)&h1, *(uint32_t*)&h2, *(uint32_t*)&h3);
    *(uint4*)dL = make_uint4(*(uint32_t*)&l0, *(uint32_t*)&l1, *(uint32_t*)&l2, *(uint32_t*)&l3);
}

// ---------------- precompute ----------------
__global__ void k_tables() {
    int i = blockIdx.x*blockDim.x + threadIdx.x;
    if (i < L1*T1) {
        int h = i / T1, t = i % T1;
        int m = (h*t) % T1;
        float a = (float)m * (1.0f/96.0f);
        g_cos1[i] = cospif(a);
        g_sin1[i] = sinpif(a);
    }
    int j = i - L1*T1;
    if (j >= 0 && j < L2*T2) {
        int h = j / T2, t = j % T2;
        int m = (h*t) % T2;
        float a = (float)m * (1.0f/48.0f);
        g_cos2[j] = cospif(a);
        g_sin2[j] = sinpif(a);
    }
}

__global__ void k_buildM(const float* __restrict__ Lc, const float* __restrict__ Lt) {
    int t = blockIdx.x, l = blockIdx.y, tp = threadIdx.x;
    float ac = 0.f, as = 0.f;
    for (int h = 0; h < L1; h++) {
        float w = (h == 0 || h == L1-1) ? (1.0f/T1) : (2.0f/T1);
        float lc = Lc[l*L1+h]*w, lt = Lt[l*L1+h]*w;
        ac = fmaf(lc * g_cos1[h*T1+t], g_cos1[h*T1+tp], ac);
        as = fmaf(lt * g_sin1[h*T1+t], g_sin1[h*T1+tp], as);
    }
    size_t o = ((size_t)l*T1 + t)*T1 + tp;
    g_Mc[o] = ac;
    g_Mt[o] = as;
}

__global__ void k_buildK1(const float* __restrict__ Wr, const float* __restrict__ Wi) {
    int i = blockIdx.x*blockDim.x + threadIdx.x;
    if (i >= CC*T1) return;
    int c = i / T1, d = i % T1;
    float acc = 0.f;
    for (int h = 0; h < L1; h++) {
        float w = (h == 0 || h == L1-1) ? (1.0f/T1) : (2.0f/T1);
        acc += w * (Wr[c*L1+h]*g_cos1[h*T1+d] - Wi[c*L1+h]*g_sin1[h*T1+d]);
    }
    g_K1[i] = acc;
}

__global__ void k_buildD1(const float* __restrict__ Wfc) {
    __shared__ float kr[2*T1];
    int t = blockIdx.x, c = blockIdx.y, s2 = threadIdx.x;
    for (int s = s2; s < T1; s += T2) {
        float v = g_K1[c*T1 + s];
        kr[s] = v; kr[s + T1] = v;
    }
    __syncthreads();
    float acc = 0.f;
    const float* kb = kr + (T1 - t);
    for (int s = 0; s < T1; s++)
        acc = fmaf(kb[s], Wfc[s*T2 + s2], acc);
    g_D1[((size_t)c*T1 + t)*T2 + s2] = acc;
}

__global__ void k_buildK2(const float* __restrict__ Wr, const float* __restrict__ Wi) {
    int i = blockIdx.x*blockDim.x + threadIdx.x;
    if (i >= CC*T2) return;
    int c = i / T2, d = i % T2;
    float acc = 0.f;
    for (int h = 0; h < L2; h++) {
        float w = (h == 0 || h == L2-1) ? (1.0f/T2) : (2.0f/T2);
        acc += w * (Wr[c*L2+h]*g_cos2[h*T2+d] - Wi[c*L2+h]*g_sin2[h*T2+d]);
    }
    g_K2[i] = acc;
}
__global__ void k_expand2() {
    size_t i = (size_t)blockIdx.x*blockDim.x + threadIdx.x;
    if (i >= (size_t)CC*T2*T2) return;
    int s = (int)(i % T2);
    int t = (int)((i / T2) % T2);
    int c = (int)(i / ((size_t)T2*T2));
    g_C2[i] = g_K2[c*T2 + ((s - t + T2) % T2)];
}

template<int KTOT, int HALVES>
__global__ void k_splitW(const float* __restrict__ W1, const float* __restrict__ W2,
                         bf16* __restrict__ dst) {
    int total = 2*HALVES*4*96*KTOT;
    int idx = blockIdx.x*blockDim.x + threadIdx.x;
    if (idx >= total) return;
    int k     = idx % KTOT;
    int n     = (idx / KTOT) % 96;
    int mat   = (idx / (KTOT*96)) % 4;
    int half  = (idx / (KTOT*96*4)) % HALVES;
    int layer = idx / (KTOT*96*4*HALVES);
    const float* src = (mat < 2) ? W1 : W2;
    int s = half*96 + n;
    float w = src[(size_t)layer*KTOT*KTOT + (size_t)k*KTOT + s];
    bf16 hi = __float2bfloat16(w);
    bf16 v = (mat & 1) ? __float2bfloat16(w - __bfloat162float(hi)) : hi;
    dst[idx] = v;
}

__global__ void k_splitMM() {
    size_t total = (size_t)CC*2*192*384;
    size_t idx = (size_t)blockIdx.x*blockDim.x + threadIdx.x;
    if (idx >= total) return;
    int k     = (int)(idx % 384);
    int n     = (int)((idx / 384) % 192);
    int plane = (int)((idx / (384*192)) % 2);
    int c     = (int)(idx / (384*192*2));
    float w = (k < 192) ? g_Mc[((size_t)c*T1 + k)*T1 + n]
                        : g_Mt[((size_t)c*T1 + (k-192))*T1 + n];
    bf16 hi = __float2bfloat16(w);
    g_McB[idx] = plane ? __float2bfloat16(w - __bfloat162float(hi)) : hi;
}

__global__ void k_splitD1() {
    int total = CC*2*96*T1;
    int idx = blockIdx.x*blockDim.x + threadIdx.x;
    if (idx >= total) return;
    int k     = idx % T1;
    int n     = (idx / T1) % 96;
    int plane = (idx / (T1*96)) % 2;
    int c     = idx / (T1*96*2);
    float w = g_D1[((size_t)c*T1 + k)*T2 + n];
    bf16 hi = __float2bfloat16(w);
    g_D1B[idx] = plane ? __float2bfloat16(w - __bfloat162float(hi)) : hi;
}

__global__ void k_splitC2() {
    int total = CC*2*96*T2;
    int idx = blockIdx.x*blockDim.x + threadIdx.x;
    if (idx >= total) return;
    int k     = idx % T2;
    int n     = (idx / T2) % 96;
    int plane = (idx / (T2*96)) % 2;
    int c     = idx / (T2*96*2);
    float w = g_C2[((size_t)c*T2 + k)*T2 + n];
    bf16 hi = __float2bfloat16(w);
    g_C2B[idx] = plane ? __float2bfloat16(w - __bfloat162float(hi)) : hi;
}

// ---------------- channel mix ----------------
__global__ void __launch_bounds__(256) k_chmix(const float* __restrict__ x,
                                               const float* __restrict__ Gc,
                                               const float* __restrict__ Gt) {
    __shared__ __align__(16) float2 sG[CC*CC];
    int tid = threadIdx.x;
    for (int i = tid; i < CC*CC; i += 256) sG[i] = make_float2(Gc[i], Gt[i]);
    __syncthreads();
    int b = blockIdx.y;
    size_t m = (size_t)blockIdx.x*256 + tid;
    ull a[CC];
#pragma unroll
    for (int l = 0; l < CC; l++) a[l] = 0ull;
    for (int c = 0; c < CC; c++) {
        float xv = x[((size_t)(b*CC + c)*NN)*T1 + m];
        ull xp = pk2(xv, xv);
#pragma unroll
        for (int l = 0; l < CC; l++) fma2(a[l], xp, *(const ull*)&sG[c*CC + l]);
    }
#pragma unroll
    for (int l = 0; l < CC; l++) {
        float2 p = upk2(a[l]);
        g_bufA[((size_t)(b*CC + l)*NN)*T1 + m] = p.x;
        g_bufB[((size_t)(b*CC + l)*NN)*T1 + m] = p.y;
    }
}

// ---------------- mm2 (tensor, merged N=192, cp.async pipeline) ----------------
// dyn smem: sA [2][hi 5120 | lo 5120] @0 (20480), sB [2][30720] @20480 (61440) => 81920
__global__ void __launch_bounds__(256) k_mm2MMA(const float* __restrict__ U,
                                                const float* __restrict__ V,
                                                const float* __restrict__ resid,
                                                float* __restrict__ Y) {
    constexpr int AST = 40;
    constexpr uint32_t ABUF = 10240, BBUF = 30720;
    extern __shared__ char sm[];
    char* sBc = sm + 20480;
    int tid = threadIdx.x, lane = tid & 31, wid = tid >> 5;
    int wm = wid & 3, wn = wid >> 2;
    int c = blockIdx.y, b = blockIdx.z;
    size_t row0 = (size_t)(b*CC + c)*NN + (size_t)blockIdx.x*64;
    const bf16* Wc = g_McB + (size_t)c*2*192*384;

    float cc[12][4];
#pragma unroll
    for (int i = 0; i < 12; i++)
#pragma unroll
        for (int j = 0; j < 4; j++) cc[i][j] = 0.f;

    uint32_t sAbase = smem_u32(sm);
    uint32_t sBbase = smem_u32(sBc);
    uint32_t aOff = (uint32_t)((wm*16 + (lane & 15))*AST + ((lane >> 4) << 3)) * 2;
    uint32_t bRow = (uint32_t)((lane & 7) + ((lane >> 4) << 3));
    uint32_t bOff = (bRow*AST + (((lane >> 3) & 1) << 3)) * 2;

    int arow = tid >> 2, akg = (tid & 3) * 8;
    uint32_t aDstOff = (uint32_t)(arow*AST + akg) * 2;

    uint32_t bDst[6];
    const bf16* bSrc[6];
#pragma unroll
    for (int it = 0; it < 6; it++) {
        int i = tid + it*256;
        int plane = i / 768, rem = i % 768;
        int n = rem >> 2, kg = (rem & 3) * 8;
        bDst[it] = (uint32_t)((plane*192 + n)*AST + kg) * 2;
        bSrc[it] = &Wc[((size_t)plane*192 + n)*384 + kg];
    }

    // prologue: stage chunk 0 (A from U, B via cp.async)
    {
        const float* xr = U + (row0 + arow)*T1 + akg;
        cvt_hilo_store(*(const float4*)xr, *(const float4*)(xr + 4),
                       (bf16*)(sm + aDstOff), (bf16*)(sm + 5120 + aDstOff));
#pragma unroll
        for (int it = 0; it < 6; it++) CP16(sBbase + bDst[it], bSrc[it]);
        CP_COMMIT();
    }

    for (int kc = 0; kc < 12; kc++) {
        uint32_t buf = (uint32_t)(kc & 1);
        float4 v0, v1;
        if (kc + 1 < 12) {
            int kn = kc + 1;
            const float* Xs = (kn < 6) ? U : V;
            int kl = (kn < 6) ? kn : kn - 6;
            const float* xr = Xs + (row0 + arow)*T1 + kl*32 + akg;
            v0 = *(const float4*)xr; v1 = *(const float4*)(xr + 4);
        }
        CP_WAIT0();
        __syncthreads();
        if (kc + 1 < 12) {
            uint32_t nb = buf ^ 1;
            cvt_hilo_store(v0, v1,
                           (bf16*)(sm + nb*ABUF + aDstOff),
                           (bf16*)(sm + nb*ABUF + 5120 + aDstOff));
#pragma unroll
            for (int it = 0; it < 6; it++)
                CP16(sBbase + nb*BBUF + bDst[it], bSrc[it] + (kc + 1)*32);
            CP_COMMIT();
        }
        uint32_t aAddrH = sAbase + buf*ABUF + aOff;
        uint32_t aAddrL = aAddrH + 5120;
        uint32_t sBcur = sBbase + buf*BBUF;
#pragma unroll
        for (int k16 = 0; k16 < 2; k16++) {
            uint32_t kof = (uint32_t)(k16 * 32);
            uint32_t ah[4], al[4];
            LDM4(ah, aAddrH + kof);
            LDM4(al, aAddrL + kof);
            uint32_t baseH = sBcur + bOff + kof;
            uint32_t baseL = baseH + (uint32_t)(192*AST)*2;
#pragma unroll
            for (int pr = 0; pr < 6; pr++) {
                uint32_t po = (uint32_t)((wn*96 + pr*16)*AST)*2;
                uint32_t bh[4], bl[4];
                LDM4(bh, baseH + po);
                LDM4(bl, baseL + po);
                MMA_BF16(cc[2*pr],   ah, bh[0], bh[1]);
                MMA_BF16(cc[2*pr+1], ah, bh[2], bh[3]);
                MMA_BF16(cc[2*pr],   al, bh[0], bh[1]);
                MMA_BF16(cc[2*pr+1], al, bh[2], bh[3]);
                MMA_BF16(cc[2*pr],   ah, bl[0], bl[1]);
                MMA_BF16(cc[2*pr+1], ah, bl[2], bl[3]);
            }
        }
    }

    int g = lane >> 2, tg = lane & 3;
    size_t mrow = row0 + (size_t)wm*16 + g;
    int colb = wn*96 + tg*2;
#pragma unroll
    for (int nf = 0; nf < 12; nf++) {
        int col = colb + nf*8;
        float2 r0 = *(const float2*)&resid[mrow*T1 + col];
        float2 r1 = *(const float2*)&resid[(mrow + 8)*T1 + col];
        *(float2*)&Y[mrow*T1 + col]       = make_float2(cc[nf][0] + r0.x, cc[nf][1] + r0.y);
        *(float2*)&Y[(mrow + 8)*T1 + col] = make_float2(cc[nf][2] + r1.x, cc[nf][3] + r1.y);
    }
}

// ---------------- channel GEMM (tensor, cp.async pipeline): Y = (X1 + sg*X2) @ W[c] [+bias] ----------------
// dyn smem: sA [2][10240] @0 (20480), sB [2][15360] @20480 (30720), sg @51200 => 51968
template<int KTOT, bool BIAS>
__global__ void __launch_bounds__(256) k_cgemmMMA(const float* __restrict__ X1,
                                                  const float* __restrict__ X2,
                                                  const bf16* __restrict__ WB,
                                                  const float* __restrict__ bias,
                                                  const float* __restrict__ gate,
                                                  float* __restrict__ Y) {
    constexpr int AST = 40, KC = KTOT/32;
    constexpr uint32_t ABUF = 10240, BBUF = 15360;
    extern __shared__ char sm[];
    char* sBc = sm + 20480;
    float* sg = (float*)(sm + 51200);
    int tid = threadIdx.x, lane = tid & 31, wid = tid >> 5;
    int wm = wid & 3, wn = wid >> 2;
    int c = blockIdx.y, b = blockIdx.z;
    size_t row0 = (size_t)(b*CC + c)*NN + (size_t)blockIdx.x*64;
    const bf16* Wc = WB + (size_t)c*2*96*KTOT;

    for (int t = tid; t < KTOT; t += 256) sg[t] = 1.0f + gate[b*KTOT + t];
    __syncthreads();

    float cc[6][4];
#pragma unroll
    for (int i = 0; i < 6; i++)
#pragma unroll
        for (int j = 0; j < 4; j++) cc[i][j] = 0.f;

    uint32_t sAbase = smem_u32(sm);
    uint32_t sBbase = smem_u32(sBc);
    uint32_t aOff = (uint32_t)((wm*16 + (lane & 15))*AST + ((lane >> 4) << 3)) * 2;
    uint32_t bRow = (uint32_t)(wn*48 + (lane & 7) + ((lane >> 4) << 3));
    uint32_t bOff = (bRow*AST + (((lane >> 3) & 1) << 3)) * 2;

    int arow = tid >> 2, akg = (tid & 3) * 8;
    const float* x1r = X1 + (row0 + arow)*KTOT;
    const float* x2r = X2 + (row0 + arow)*KTOT;
    uint32_t aDstOff = (uint32_t)(arow*AST + akg) * 2;

    uint32_t bDst[3];
    const bf16* bSrc[3];
#pragma unroll
    for (int it = 0; it < 3; it++) {
        int i = tid + it*256;
        int plane = i / 384, rem = i % 384;
        int n = rem >> 2, kg = (rem & 3) * 8;
        bDst[it] = (uint32_t)((plane*96 + n)*AST + kg) * 2;
        bSrc[it] = &Wc[((size_t)plane*96 + n)*KTOT + kg];
    }

    // prologue: stage chunk 0
    {
        float4 v0 = *(const float4*)&x1r[akg];
        float4 v1 = *(const float4*)&x1r[akg + 4];
        float4 u0 = *(const float4*)&x2r[akg];
        float4 u1 = *(const float4*)&x2r[akg + 4];
        v0.x = fmaf(u0.x, sg[akg],   v0.x);
        v0.y = fmaf(u0.y, sg[akg+1], v0.y);
        v0.z = fmaf(u0.z, sg[akg+2], v0.z);
        v0.w = fmaf(u0.w, sg[akg+3], v0.w);
        v1.x = fmaf(u1.x, sg[akg+4], v1.x);
        v1.y = fmaf(u1.y, sg[akg+5], v1.y);
        v1.z = fmaf(u1.z, sg[akg+6], v1.z);
        v1.w = fmaf(u1.w, sg[akg+7], v1.w);
        cvt_hilo_store(v0, v1, (bf16*)(sm + aDstOff), (bf16*)(sm + 5120 + aDstOff));
#pragma unroll
        for (int it = 0; it < 3; it++) CP16(sBbase + bDst[it], bSrc[it]);
        CP_COMMIT();
    }

    for (int kc = 0; kc < KC; kc++) {
        uint32_t buf = (uint32_t)(kc & 1);
        float4 v0, v1, u0, u1;
        if (kc + 1 < KC) {
            int kn = (kc + 1)*32 + akg;
            v0 = *(const float4*)&x1r[kn];
            v1 = *(const float4*)&x1r[kn + 4];
            u0 = *(const float4*)&x2r[kn];
            u1 = *(const float4*)&x2r[kn + 4];
        }
        CP_WAIT0();
        __syncthreads();
        if (kc + 1 < KC) {
            uint32_t nb = buf ^ 1;
            int k0 = (kc + 1)*32 + akg;
            v0.x = fmaf(u0.x, sg[k0],   v0.x);
            v0.y = fmaf(u0.y, sg[k0+1], v0.y);
            v0.z = fmaf(u0.z, sg[k0+2], v0.z);
            v0.w = fmaf(u0.w, sg[k0+3], v0.w);
            v1.x = fmaf(u1.x, sg[k0+4], v1.x);
            v1.y = fmaf(u1.y, sg[k0+5], v1.y);
            v1.z = fmaf(u1.z, sg[k0+6], v1.z);
            v1.w = fmaf(u1.w, sg[k0+7], v1.w);
            cvt_hilo_store(v0, v1,
                           (bf16*)(sm + nb*ABUF + aDstOff),
                           (bf16*)(sm + nb*ABUF + 5120 + aDstOff));
#pragma unroll
            for (int it = 0; it < 3; it++)
                CP16(sBbase + nb*BBUF + bDst[it], bSrc[it] + (kc + 1)*32);
            CP_COMMIT();
        }
        uint32_t aAddrH = sAbase + buf*ABUF + aOff;
        uint32_t aAddrL = aAddrH + 5120;
        uint32_t sBcur = sBbase + buf*BBUF;
#pragma unroll
        for (int k16 = 0; k16 < 2; k16++) {
            uint32_t kof = (uint32_t)(k16 * 32);
            uint32_t ah[4], al[4];
            LDM4(ah, aAddrH + kof);
            LDM4(al, aAddrL + kof);
            uint32_t baseH = sBcur + bOff + kof;
            uint32_t baseL = baseH + (uint32_t)(96*AST)*2;
#pragma unroll
            for (int pr = 0; pr < 3; pr++) {
                uint32_t po = (uint32_t)(pr*16*AST)*2;
                uint32_t bh[4], bl[4];
                LDM4(bh, baseH + po);
                LDM4(bl, baseL + po);
                MMA_BF16(cc[2*pr],   ah, bh[0], bh[1]);
                MMA_BF16(cc[2*pr+1], ah, bh[2], bh[3]);
                MMA_BF16(cc[2*pr],   al, bh[0], bh[1]);
                MMA_BF16(cc[2*pr+1], al, bh[2], bh[3]);
                MMA_BF16(cc[2*pr],   ah, bl[0], bl[1]);
                MMA_BF16(cc[2*pr+1], ah, bl[2], bl[3]);
            }
        }
    }

    int g = lane >> 2, tg = lane & 3;
    size_t mrow = row0 + (size_t)wm*16 + g;
    int colb = wn*48 + tg*2;
#pragma unroll
    for (int nf = 0; nf < 6; nf++) {
        int col = colb + nf*8;
        float2 o0 = make_float2(cc[nf][0], cc[nf][1]);
        float2 o1 = make_float2(cc[nf][2], cc[nf][3]);
        if (BIAS) {
            float2 bv = *(const float2*)&bias[col];
            o0.x += bv.x; o0.y += bv.y; o1.x += bv.x; o1.y += bv.y;
        }
        *(float2*)&Y[mrow*96 + col]       = o0;
        *(float2*)&Y[(mrow + 8)*96 + col] = o1;
    }
}

// ---------------- tensor gmlp: cp.async double-buffered pipeline (R15, cleaned) ----------------
// dyn smem: sA [2][hi 5120 | lo 5120] @0 (20480), sB [2][30720] @20480 (61440),
//           sg @81920 (<=768), sFP @82688 (1536)  => 84224
template<int KTOT, bool G1>
__global__ void __launch_bounds__(256) k_gmlpMMA(const float* __restrict__ X,
                                                 const bf16* __restrict__ Bw,
                                                 const float* __restrict__ gate,
                                                 float* __restrict__ Y) {
    constexpr int KC = KTOT/32;
    constexpr int AST = 40;
    constexpr uint32_t ABUF = 10240, BBUF = 30720;
    extern __shared__ char sm[];
    char* sBc = sm + 20480;
    float* sg = (float*)(sm + 81920);
    float (*sFP)[48] = (float(*)[48])(sm + 82688);
    int tid = threadIdx.x, lane = tid & 31, wid = tid >> 5;
    int wm = wid & 3, wn = wid >> 2;
    int half = blockIdx.y;
    int tix = blockIdx.x;
    size_t row0 = (size_t)tix * 64;
    int b = tix >> 8;
    int ch = (tix >> 3) & 31;
    int tile = tix & 7;
    const bf16* BwH = Bw + (size_t)half * 4*96*KTOT;

    if (G1) {
        for (int t = tid; t < KTOT; t += 256) sg[t] = 1.0f + gate[b*KTOT + t];
        __syncthreads();
    }

    float c1[6][4], c2[6][4];
#pragma unroll
    for (int i = 0; i < 6; i++)
#pragma unroll
        for (int j = 0; j < 4; j++) { c1[i][j] = 0.f; c2[i][j] = 0.f; }

    uint32_t sAbase = smem_u32(sm);
    uint32_t sBbase = smem_u32(sBc);
    uint32_t aOff = (uint32_t)((wm*16 + (lane & 15))*AST + ((lane >> 4) << 3)) * 2;
    uint32_t bRow = (uint32_t)(wn*48 + (lane & 7) + ((lane >> 4) << 3));
    uint32_t bOff = (bRow*AST + (((lane >> 3) & 1) << 3)) * 2;

    int arow = tid >> 2, akg = (tid & 3) * 8;
    const float* xrow = X + (row0 + arow)*KTOT;
    uint32_t aDstOff = (uint32_t)(arow*AST + akg) * 2;

    uint32_t bDst[6];
    const bf16* bSrc[6];
#pragma unroll
    for (int it = 0; it < 6; it++) {
        int i = tid + it*256;
        int mat = i / 384, rem = i % 384;
        int n = rem >> 2, kg = (rem & 3) * 8;
        bDst[it] = (uint32_t)((mat*96 + n)*AST + kg) * 2;
        bSrc[it] = &BwH[((size_t)mat*96 + n)*KTOT + kg];
    }

    // prologue: stage chunk 0 into buffer 0
    {
        float4 v0 = *(const float4*)&xrow[akg];
        float4 v1 = *(const float4*)&xrow[akg + 4];
        if (G1) {
            v0.x *= sg[akg];   v0.y *= sg[akg+1]; v0.z *= sg[akg+2]; v0.w *= sg[akg+3];
            v1.x *= sg[akg+4]; v1.y *= sg[akg+5]; v1.z *= sg[akg+6]; v1.w *= sg[akg+7];
        }
        cvt_hilo_store(v0, v1, (bf16*)(sm + aDstOff), (bf16*)(sm + 5120 + aDstOff));
#pragma unroll
        for (int it = 0; it < 6; it++) CP16(sBbase + bDst[it], bSrc[it]);
        CP_COMMIT();
    }

    for (int kc = 0; kc < KC; kc++) {
        uint32_t buf = (uint32_t)(kc & 1);
        float4 v0, v1;
        if (kc + 1 < KC) {
            int kn = (kc + 1)*32;
            v0 = *(const float4*)&xrow[kn + akg];
            v1 = *(const float4*)&xrow[kn + akg + 4];
        }
        CP_WAIT0();
        __syncthreads();
        if (kc + 1 < KC) {
            uint32_t nb = buf ^ 1;
            int k0 = (kc + 1)*32 + akg;
            if (G1) {
                v0.x *= sg[k0];   v0.y *= sg[k0+1]; v0.z *= sg[k0+2]; v0.w *= sg[k0+3];
                v1.x *= sg[k0+4]; v1.y *= sg[k0+5]; v1.z *= sg[k0+6]; v1.w *= sg[k0+7];
            }
            cvt_hilo_store(v0, v1,
                           (bf16*)(sm + nb*ABUF + aDstOff),
                           (bf16*)(sm + nb*ABUF + 5120 + aDstOff));
#pragma unroll
            for (int it = 0; it < 6; it++)
                CP16(sBbase + nb*BBUF + bDst[it], bSrc[it] + (kc + 1)*32);
            CP_COMMIT();
        }
        uint32_t aAddrH = sAbase + buf*ABUF + aOff;
        uint32_t aAddrL = aAddrH + 5120;
        uint32_t sBcur = sBbase + buf*BBUF;
#pragma unroll
        for (int k16 = 0; k16 < 2; k16++) {
            uint32_t kof = (uint32_t)(k16 * 32);
            uint32_t ah[4], al[4];
            LDM4(ah, aAddrH + kof);
            LDM4(al, aAddrL + kof);
#pragma unroll
            for (int mat = 0; mat < 2; mat++) {
                float (*cf)[4] = mat ? c2 : c1;
                uint32_t baseH = sBcur + (uint32_t)((mat*2 + 0)*96*AST)*2 + bOff + kof;
                uint32_t baseL = sBcur + (uint32_t)((mat*2 + 1)*96*AST)*2 + bOff + kof;
#pragma unroll
                for (int pr = 0; pr < 3; pr++) {
                    uint32_t po = (uint32_t)(pr*16*AST)*2;
                    uint32_t bh[4], bl[4];
                    LDM4(bh, baseH + po);
                    LDM4(bl, baseL + po);
                    MMA_BF16(cf[2*pr],   ah, bh[0], bh[1]);
                    MMA_BF16(cf[2*pr+1], ah, bh[2], bh[3]);
                    MMA_BF16(cf[2*pr],   al, bh[0], bh[1]);
                    MMA_BF16(cf[2*pr+1], al, bh[2], bh[3]);
                    MMA_BF16(cf[2*pr],   ah, bl[0], bl[1]);
                    MMA_BF16(cf[2*pr+1], ah, bl[2], bl[3]);
                }
            }
        }
    }

    // epilogue: o = (X@W1)*gelu(X@W2), store + column partial sums
    __syncthreads();
    int g = lane >> 2, tg = lane & 3;
    size_t mrow = row0 + (size_t)wm*16 + g;
    int colb = half*96 + wn*48 + tg*2;
    float colsum[12];
#pragma unroll
    for (int nf = 0; nf < 6; nf++) {
        int col = colb + nf*8;
        float2 o0 = make_float2(c1[nf][0]*gelu_t(c2[nf][0]), c1[nf][1]*gelu_t(c2[nf][1]));
        float2 o1 = make_float2(c1[nf][2]*gelu_t(c2[nf][2]), c1[nf][3]*gelu_t(c2[nf][3]));
        *(float2*)&Y[mrow*KTOT + col] = o0;
        *(float2*)&Y[(mrow + 8)*KTOT + col] = o1;
        colsum[2*nf]   = o0.x + o1.x;
        colsum[2*nf+1] = o0.y + o1.y;
    }
#pragma unroll
    for (int i = 0; i < 12; i++) {
        float v = colsum[i];
        v += __shfl_xor_sync(0xFFFFFFFF, v, 16);
        v += __shfl_xor_sync(0xFFFFFFFF, v, 8);
        v += __shfl_xor_sync(0xFFFFFFFF, v, 4);
        colsum[i] = v;
    }
    if (lane < 4) {
#pragma unroll
        for (int nf = 0; nf < 6; nf++) {
            sFP[wid][lane*2 + nf*8]     = colsum[2*nf];
            sFP[wid][lane*2 + nf*8 + 1] = colsum[2*nf+1];
        }
    }
    __syncthreads();
    if (tid < 96) {
        int wn2 = tid / 48, idx = tid % 48;
        float tot = sFP[wn2*4+0][idx] + sFP[wn2*4+1][idx] + sFP[wn2*4+2][idx] + sFP[wn2*4+3][idx];
        g_featP[((size_t)(b*CC + ch)*8 + tile)*KTOT + half*96 + wn2*48 + idx] = tot;
    }
}

// ---------------- attn gate (reads featP partials, 8 tiles) ----------------
template<int T>
__global__ void __launch_bounds__(T) k_gate(const float* __restrict__ Wq,
                                            const float* __restrict__ Wk) {
    __shared__ float ks[T][EE];
    int b = blockIdx.x, t = threadIdx.x;
    float q[EE], kk[EE];
#pragma unroll
    for (int e = 0; e < EE; e++) { q[e] = 0.f; kk[e] = 0.f; }
    for (int c = 0; c < CC; c++) {
        float f = 0.f;
#pragma unroll
        for (int p = 0; p < 8; p++) f += g_featP[((size_t)(b*CC + c)*8 + p)*T + t];
        f *= (1.0f/NN);
#pragma unroll
        for (int e = 0; e < EE; e++) {
            q[e]  = fmaf(f, Wq[c*EE + e], q[e]);
            kk[e] = fmaf(f, Wk[c*EE + e], kk[e]);
        }
    }
#pragma unroll
    for (int e = 0; e < EE; e++) ks[t][e] = kk[e];
    __syncthreads();
    float smax = -1e30f, stt = 0.f;
    for (int j = 0; j < T; j++) {
        float d = 0.f;
#pragma unroll
        for (int e = 0; e < EE; e++) d = fmaf(q[e], ks[j][e], d);
        d *= 0.125f;
        if (j == t) stt = d;
        smax = fmaxf(smax, d);
    }
    float ssum = 0.f;
    for (int j = 0; j < T; j++) {
        float d = 0.f;
#pragma unroll
        for (int e = 0; e < EE; e++) d = fmaf(q[e], ks[j][e], d);
        ssum += expf(d*0.125f - smax);
    }
    float p = expf(stt - smax) / ssum;
    g_gate[b*T + t] = gelu_t(p);
}

// ---------------- driver ----------------
extern "C" void kernel_launch(void* const* d_in, const int* in_sizes, int n_in,
                              void* d_out, int out_size) {
    const float* x   = (const float*)d_in[0];
    const float* Gc  = (const float*)d_in[3];
    const float* Lc  = (const float*)d_in[4];
    const float* Gt  = (const float*)d_in[5];
    const float* Lt  = (const float*)d_in[6];
    const float* f1r = (const float*)d_in[7];
    const float* f1i = (const float*)d_in[8];
    const float* f2r = (const float*)d_in[9];
    const float* f2i = (const float*)d_in[10];
    const float* Wfc = (const float*)d_in[11];
    const float* bfc = (const float*)d_in[12];
    const float* mi1 = (const float*)d_in[13];
    const float* mi2 = (const float*)d_in[14];
    const float* mo1 = (const float*)d_in[15];
    const float* mo2 = (const float*)d_in[16];
    const float* aiq = (const float*)d_in[17];
    const float* aik = (const float*)d_in[18];
    const float* aoq = (const float*)d_in[19];
    const float* aok = (const float*)d_in[20];
    float* out = (float*)d_out;

    float *bufA, *bufB, *bufC, *bufD, *bufF, *gate;
    bf16 *Bin, *Bout, *D1B, *C2B;
    cudaGetSymbolAddress((void**)&bufA, g_bufA);
    cudaGetSymbolAddress((void**)&bufB, g_bufB);
    cudaGetSymbolAddress((void**)&bufC, g_bufC);
    cudaGetSymbolAddress((void**)&bufD, g_bufD);
    cudaGetSymbolAddress((void**)&bufF, g_bufF);
    cudaGetSymbolAddress((void**)&gate, g_gate);
    cudaGetSymbolAddress((void**)&Bin,  g_Bin);
    cudaGetSymbolAddress((void**)&Bout, g_Bout);
    cudaGetSymbolAddress((void**)&D1B,  g_D1B);
    cudaGetSymbolAddress((void**)&C2B,  g_C2B);

    constexpr int SMEM_G = 84224;
    constexpr int SMEM_M = 81920;
    constexpr int SMEM_C = 51968;
    cudaFuncSetAttribute(k_gmlpMMA<T1,false>, cudaFuncAttributeMaxDynamicSharedMemorySize, SMEM_G);
    cudaFuncSetAttribute(k_gmlpMMA<T1,true >, cudaFuncAttributeMaxDynamicSharedMemorySize, SMEM_G);
    cudaFuncSetAttribute(k_gmlpMMA<T2,false>, cudaFuncAttributeMaxDynamicSharedMemorySize, SMEM_G);
    cudaFuncSetAttribute(k_gmlpMMA<T2,true >, cudaFuncAttributeMaxDynamicSharedMemorySize, SMEM_G);
    cudaFuncSetAttribute(k_mm2MMA, cudaFuncAttributeMaxDynamicSharedMemorySize, SMEM_M);
    cudaFuncSetAttribute(k_cgemmMMA<T1,true >, cudaFuncAttributeMaxDynamicSharedMemorySize, SMEM_C);
    cudaFuncSetAttribute(k_cgemmMMA<T2,false>, cudaFuncAttributeMaxDynamicSharedMemorySize, SMEM_C);

    // precompute operator matrices + weight splits
    k_tables<<<(L1*T1 + L2*T2 + 255)/256, 256>>>();
    k_buildM<<<dim3(T1, CC), T1>>>(Lc, Lt);
    k_buildK1<<<(CC*T1 + 255)/256, 256>>>(f1r, f1i);
    k_buildD1<<<dim3(T1, CC), T2>>>(Wfc);
    k_buildK2<<<(CC*T2 + 255)/256, 256>>>(f2r, f2i);
    k_expand2<<<(int)(((size_t)CC*T2*T2 + 255)/256), 256>>>();
    k_splitW<T1,2><<<(2*2*4*96*T1 + 255)/256, 256>>>(mi1, mi2, Bin);
    k_splitW<T2,1><<<(2*1*4*96*T2 + 255)/256, 256>>>(mo1, mo2, Bout);
    k_splitMM<<<(int)(((size_t)CC*2*192*384 + 255)/256), 256>>>();
    k_splitD1<<<(CC*2*96*T1 + 255)/256, 256>>>();
    k_splitC2<<<(CC*2*96*T2 + 255)/256, 256>>>();

    // freq_attn_in: u = Gc^T x, v = Gt^T x ; xc = x + u@Mc[c] + v@Mt[c]
    k_chmix<<<dim3(NN*T1/256, BB), 256>>>(x, Gc, Gt);
    k_mm2MMA<<<dim3(NN/64, CC, BB), 256, SMEM_M>>>(bufA, bufB, x, bufC);

    const int NT = BB*CC*NN/64;               // 4096 M-tiles of 64 rows
    const size_t L1OFF = (size_t)2*4*96*T1;
    const size_t L2OFF = (size_t)1*4*96*T2;

    // input-side layers (tensor core, cp.async pipeline, n-mean fused)
    k_gmlpMMA<T1,false><<<dim3(NT, 2), 256, SMEM_G>>>(bufC, Bin, nullptr, bufA);
    k_gate<T1><<<BB, T1>>>(aiq, aik);
    k_gmlpMMA<T1,true ><<<dim3(NT, 2), 256, SMEM_G>>>(bufA, Bin + L1OFF, gate, bufC);
    k_gate<T1><<<BB, T1>>>(aiq + CC*EE, aik + CC*EE);

    // h_y = (x + xc*(1+g)) @ D1[c] + bfc   (fconv1 + fc_idp fused, tensor, pipelined)
    k_cgemmMMA<T1, true><<<dim3(NN/64, CC, BB), 256, SMEM_C>>>(x, bufC, D1B, bfc, gate, bufD);

    // output-side layers (tensor core, cp.async pipeline, n-mean fused)
    k_gmlpMMA<T2,false><<<dim3(NT, 1), 256, SMEM_G>>>(bufD, Bout, nullptr, bufA);
    k_gate<T2><<<BB, T2>>>(aoq, aok);
    k_gmlpMMA<T2,true ><<<dim3(NT, 1), 256, SMEM_G>>>(bufA, Bout + L2OFF, gate, bufF);
    k_gate<T2><<<BB, T2>>>(aoq + CC*EE, aok + CC*EE);

    // out = (h_y + y_c*(1+g)) @ C2[c]   (tensor, pipelined)
    k_cgemmMMA<T2, false><<<dim3(NN/64, CC, BB), 256, SMEM_C>>>(bufD, bufF, C2B, nullptr, gate, out);
}

// round 17
// speedup vs baseline: 1.0725x; 1.0082x over previous
#include <cuda_runtime.h>
#include <cuda_bf16.h>
#include <math.h>
#include <stdint.h>

#define BB 16
#define CC 32
#define NN 512
#define T1 192
#define T2 96
#define L1 97
#define L2 49
#define EE 64

typedef unsigned long long ull;
typedef __nv_bfloat16 bf16;

static constexpr size_t SZ1 = (size_t)BB*CC*NN*T1;
static constexpr size_t SZ2 = (size_t)BB*CC*NN*T2;

// ---------------- scratch ----------------
__device__ float g_bufA[SZ1];
__device__ float g_bufB[SZ1];
__device__ float g_bufC[SZ1];
__device__ float g_bufD[SZ2];
__device__ float g_bufF[SZ2];
__device__ float g_cos1[L1*T1];
__device__ float g_sin1[L1*T1];
__device__ float g_cos2[L2*T2];
__device__ float g_sin2[L2*T2];
__device__ float g_K1[CC*T1];
__device__ float g_K2[CC*T2];
__device__ float g_featP[BB*CC*8*T1];
__device__ float g_gate[BB*T1];
// pre-split bf16 weights
__device__ bf16 g_Bin[2*2*4*96*T1];
__device__ bf16 g_Bout[2*1*4*96*T2];
__device__ bf16 g_McB[CC*2*192*384];
__device__ bf16 g_D1B[CC*2*96*T1];
__device__ bf16 g_C2B[CC*2*96*T2];

// ---------------- f32x2 helpers ----------------
__device__ __forceinline__ ull pk2(float lo, float hi) {
    ull r; asm("mov.b64 %0, {%1,%2};" : "=l"(r) : "f"(lo), "f"(hi)); return r;
}
__device__ __forceinline__ void fma2(ull& d, ull a, ull b) {
    asm("fma.rn.f32x2 %0, %1, %2, %0;" : "+l"(d) : "l"(a), "l"(b));
}
__device__ __forceinline__ float2 upk2(ull v) {
    float2 f; asm("mov.b64 {%0,%1}, %2;" : "=f"(f.x), "=f"(f.y) : "l"(v)); return f;
}

__device__ __forceinline__ float gelu_t(float x) {
    float x3 = x*x*x;
    return 0.5f*x*(1.0f + tanhf(0.7978845608028654f*(x + 0.044715f*x3)));
}

__device__ __forceinline__ uint32_t smem_u32(const void* p) {
    uint32_t a;
    asm("{ .reg .u64 t; cvta.to.shared.u64 t, %1; cvt.u32.u64 %0, t; }" : "=r"(a) : "l"(p));
    return a;
}

// ---------------- mma.sync / cp.async helpers ----------------
#define LDM4(r, addr) \
    asm volatile("ldmatrix.sync.aligned.m8n8.x4.shared.b16 {%0,%1,%2,%3}, [%4];" \
        : "=r"((r)[0]), "=r"((r)[1]), "=r"((r)[2]), "=r"((r)[3]) : "r"(addr))

#define MMA_BF16(c, a, b0, b1) \
    asm volatile("mma.sync.aligned.m16n8k16.row.col.f32.bf16.bf16.f32 " \
        "{%0,%1,%2,%3},{%4,%5,%6,%7},{%8,%9},{%0,%1,%2,%3};" \
        : "+f"((c)[0]), "+f"((c)[1]), "+f"((c)[2]), "+f"((c)[3]) \
        : "r"((a)[0]), "r"((a)[1]), "r"((a)[2]), "r"((a)[3]), "r"(b0), "r"(b1))

#define CP16(dst, src) \
    asm volatile("cp.async.cg.shared.global [%0], [%1], 16;" :: "r"(dst), "l"(src))
#define CP_COMMIT() asm volatile("cp.async.commit_group;" ::: "memory")
#define CP_WAIT0()  asm volatile("cp.async.wait_group 0;" ::: "memory")

__device__ __forceinline__ void cvt_hilo_store(float4 v0, float4 v1, bf16* dH, bf16* dL) {
    __nv_bfloat162 h0 = __floats2bfloat162_rn(v0.x, v0.y);
    __nv_bfloat162 h1 = __floats2bfloat162_rn(v0.z, v0.w);
    __nv_bfloat162 h2 = __floats2bfloat162_rn(v1.x, v1.y);
    __nv_bfloat162 h3 = __floats2bfloat162_rn(v1.z, v1.w);
    __nv_bfloat162 l0 = __floats2bfloat162_rn(v0.x - __bfloat162float(h0.x), v0.y - __bfloat162float(h0.y));
    __nv_bfloat162 l1 = __floats2bfloat162_rn(v0.z - __bfloat162float(h1.x), v0.w - __bfloat162float(h1.y));
    __nv_bfloat162 l2 = __floats2bfloat162_rn(v1.x - __bfloat162float(h2.x), v1.y - __bfloat162float(h2.y));
    __nv_bfloat162 l3 = __floats2bfloat162_rn(v1.z - __bfloat162float(h3.x), v1.w - __bfloat162float(h3.y));
    *(uint4*)dH = make_uint4(*(uint32_t*)&h0, *(uint32_t*)&h1, *(uint32_t*)&h2, *(uint32_t*)&h3);
    *(uint4*)dL = make_uint4(*(uint32_t*)&l0, *(uint32_t*)&l1, *(uint32_t*)&l2, *(uint32_t*)&l3);
}

// ---------------- precompute ----------------
__global__ void k_tables() {
    int i = blockIdx.x*blockDim.x + threadIdx.x;
    if (i < L1*T1) {
        int h = i / T1, t = i % T1;
        int m = (h*t) % T1;
        float a = (float)m * (1.0f/96.0f);
        g_cos1[i] = cospif(a);
        g_sin1[i] = sinpif(a);
    }
    int j = i - L1*T1;
    if (j >= 0 && j < L2*T2) {
        int h = j / T2, t = j % T2;
        int m = (h*t) % T2;
        float a = (float)m * (1.0f/48.0f);
        g_cos2[j] = cospif(a);
        g_sin2[j] = sinpif(a);
    }
}

// fused buildM + splitMM: writes g_McB[c][plane][n][k] directly (bf16 hi/lo).
// value at (l, k=t, n): Mc[l][t][n] (k<192) / Mt (k>=192). Thread = t -> k contiguous, coalesced.
__global__ void k_buildMB(const float* __restrict__ Lc, const float* __restrict__ Lt) {
    int n = blockIdx.x, l = blockIdx.y, t = threadIdx.x;
    float ac = 0.f, as = 0.f;
    for (int h = 0; h < L1; h++) {
        float w = (h == 0 || h == L1-1) ? (1.0f/T1) : (2.0f/T1);
        float lc = Lc[l*L1+h]*w, lt = Lt[l*L1+h]*w;
        ac = fmaf(lc * g_cos1[h*T1+t], g_cos1[h*T1+n], ac);
        as = fmaf(lt * g_sin1[h*T1+t], g_sin1[h*T1+n], as);
    }
    size_t base = (size_t)l*2*192*384;
    bf16 hc = __float2bfloat16(ac);
    bf16 lc2 = __float2bfloat16(ac - __bfloat162float(hc));
    bf16 ht = __float2bfloat16(as);
    bf16 lt2 = __float2bfloat16(as - __bfloat162float(ht));
    g_McB[base + (size_t)n*384 + t]                     = hc;
    g_McB[base + (size_t)192*384 + (size_t)n*384 + t]   = lc2;
    g_McB[base + (size_t)n*384 + 192 + t]               = ht;
    g_McB[base + (size_t)192*384 + (size_t)n*384 + 192 + t] = lt2;
}

__global__ void k_buildK1(const float* __restrict__ Wr, const float* __restrict__ Wi) {
    int i = blockIdx.x*blockDim.x + threadIdx.x;
    if (i >= CC*T1) return;
    int c = i / T1, d = i % T1;
    float acc = 0.f;
    for (int h = 0; h < L1; h++) {
        float w = (h == 0 || h == L1-1) ? (1.0f/T1) : (2.0f/T1);
        acc += w * (Wr[c*L1+h]*g_cos1[h*T1+d] - Wi[c*L1+h]*g_sin1[h*T1+d]);
    }
    g_K1[i] = acc;
}

// fused buildD1 + splitD1: D1B[c][plane][n=s2][k=t] = split( sum_s K1[c][(s-t)%192] * Wfc[s][s2] )
// grid (96 = s2, CC), block 192 (t) -> coalesced stores over k.
__global__ void k_buildD1B(const float* __restrict__ Wfc) {
    __shared__ float kr[2*T1];
    __shared__ float wcol[T1];
    int s2 = blockIdx.x, c = blockIdx.y, t = threadIdx.x;
    {
        float v = g_K1[c*T1 + t];
        kr[t] = v; kr[t + T1] = v;
        wcol[t] = Wfc[t*T2 + s2];
    }
    __syncthreads();
    float acc = 0.f;
    const float* kb = kr + (T1 - t);
    for (int s = 0; s < T1; s++)
        acc = fmaf(kb[s], wcol[s], acc);
    bf16 hi = __float2bfloat16(acc);
    bf16 lo = __float2bfloat16(acc - __bfloat162float(hi));
    g_D1B[((size_t)(c*2 + 0)*96 + s2)*T1 + t] = hi;
    g_D1B[((size_t)(c*2 + 1)*96 + s2)*T1 + t] = lo;
}

__global__ void k_buildK2(const float* __restrict__ Wr, const float* __restrict__ Wi) {
    int i = blockIdx.x*blockDim.x + threadIdx.x;
    if (i >= CC*T2) return;
    int c = i / T2, d = i % T2;
    float acc = 0.f;
    for (int h = 0; h < L2; h++) {
        float w = (h == 0 || h == L2-1) ? (1.0f/T2) : (2.0f/T2);
        acc += w * (Wr[c*L2+h]*g_cos2[h*T2+d] - Wi[c*L2+h]*g_sin2[h*T2+d]);
    }
    g_K2[i] = acc;
}

// fused expand2 + splitC2: C2B[c][plane][n][k] = split( K2[c][(n-k+96)%96] )
// grid (96 = n, CC), block 96 (k) -> coalesced.
__global__ void k_buildC2B() {
    __shared__ float kr[2*T2];
    int n = blockIdx.x, c = blockIdx.y, k = threadIdx.x;
    {
        float v = g_K2[c*T2 + k];
        kr[k] = v; kr[k + T2] = v;
    }
    __syncthreads();
    float w = kr[n - k + T2];
    bf16 hi = __float2bfloat16(w);
    bf16 lo = __float2bfloat16(w - __bfloat162float(hi));
    g_C2B[((size_t)(c*2 + 0)*96 + n)*T2 + k] = hi;
    g_C2B[((size_t)(c*2 + 1)*96 + n)*T2 + k] = lo;
}

template<int KTOT, int HALVES>
__global__ void k_splitW(const float* __restrict__ W1, const float* __restrict__ W2,
                         bf16* __restrict__ dst) {
    int total = 2*HALVES*4*96*KTOT;
    int idx = blockIdx.x*blockDim.x + threadIdx.x;
    if (idx >= total) return;
    int k     = idx % KTOT;
    int n     = (idx / KTOT) % 96;
    int mat   = (idx / (KTOT*96)) % 4;
    int half  = (idx / (KTOT*96*4)) % HALVES;
    int layer = idx / (KTOT*96*4*HALVES);
    const float* src = (mat < 2) ? W1 : W2;
    int s = half*96 + n;
    float w = src[(size_t)layer*KTOT*KTOT + (size_t)k*KTOT + s];
    bf16 hi = __float2bfloat16(w);
    bf16 v = (mat & 1) ? __float2bfloat16(w - __bfloat162float(hi)) : hi;
    dst[idx] = v;
}

// ---------------- channel mix ----------------
__global__ void __launch_bounds__(256) k_chmix(const float* __restrict__ x,
                                               const float* __restrict__ Gc,
                                               const float* __restrict__ Gt) {
    __shared__ __align__(16) float2 sG[CC*CC];
    int tid = threadIdx.x;
    for (int i = tid; i < CC*CC; i += 256) sG[i] = make_float2(Gc[i], Gt[i]);
    __syncthreads();
    int b = blockIdx.y;
    size_t m = (size_t)blockIdx.x*256 + tid;
    ull a[CC];
#pragma unroll
    for (int l = 0; l < CC; l++) a[l] = 0ull;
    for (int c = 0; c < CC; c++) {
        float xv = x[((size_t)(b*CC + c)*NN)*T1 + m];
        ull xp = pk2(xv, xv);
#pragma unroll
        for (int l = 0; l < CC; l++) fma2(a[l], xp, *(const ull*)&sG[c*CC + l]);
    }
#pragma unroll
    for (int l = 0; l < CC; l++) {
        float2 p = upk2(a[l]);
        g_bufA[((size_t)(b*CC + l)*NN)*T1 + m] = p.x;
        g_bufB[((size_t)(b*CC + l)*NN)*T1 + m] = p.y;
    }
}

// ---------------- mm2 (tensor, merged N=192, cp.async pipeline) ----------------
// dyn smem: sA [2][hi 5120 | lo 5120] @0 (20480), sB [2][30720] @20480 (61440) => 81920
__global__ void __launch_bounds__(256) k_mm2MMA(const float* __restrict__ U,
                                                const float* __restrict__ V,
                                                const float* __restrict__ resid,
                                                float* __restrict__ Y) {
    constexpr int AST = 40;
    constexpr uint32_t ABUF = 10240, BBUF = 30720;
    extern __shared__ char sm[];
    char* sBc = sm + 20480;
    int tid = threadIdx.x, lane = tid & 31, wid = tid >> 5;
    int wm = wid & 3, wn = wid >> 2;
    int c = blockIdx.y, b = blockIdx.z;
    size_t row0 = (size_t)(b*CC + c)*NN + (size_t)blockIdx.x*64;
    const bf16* Wc = g_McB + (size_t)c*2*192*384;

    float cc[12][4];
#pragma unroll
    for (int i = 0; i < 12; i++)
#pragma unroll
        for (int j = 0; j < 4; j++) cc[i][j] = 0.f;

    uint32_t sAbase = smem_u32(sm);
    uint32_t sBbase = smem_u32(sBc);
    uint32_t aOff = (uint32_t)((wm*16 + (lane & 15))*AST + ((lane >> 4) << 3)) * 2;
    uint32_t bRow = (uint32_t)((lane & 7) + ((lane >> 4) << 3));
    uint32_t bOff = (bRow*AST + (((lane >> 3) & 1) << 3)) * 2;

    int arow = tid >> 2, akg = (tid & 3) * 8;
    uint32_t aDstOff = (uint32_t)(arow*AST + akg) * 2;

    uint32_t bDst[6];
    const bf16* bSrc[6];
#pragma unroll
    for (int it = 0; it < 6; it++) {
        int i = tid + it*256;
        int plane = i / 768, rem = i % 768;
        int n = rem >> 2, kg = (rem & 3) * 8;
        bDst[it] = (uint32_t)((plane*192 + n)*AST + kg) * 2;
        bSrc[it] = &Wc[((size_t)plane*192 + n)*384 + kg];
    }

    // prologue: stage chunk 0 (A from U, B via cp.async)
    {
        const float* xr = U + (row0 + arow)*T1 + akg;
        cvt_hilo_store(*(const float4*)xr, *(const float4*)(xr + 4),
                       (bf16*)(sm + aDstOff), (bf16*)(sm + 5120 + aDstOff));
#pragma unroll
        for (int it = 0; it < 6; it++) CP16(sBbase + bDst[it], bSrc[it]);
        CP_COMMIT();
    }

    for (int kc = 0; kc < 12; kc++) {
        uint32_t buf = (uint32_t)(kc & 1);
        float4 v0, v1;
        if (kc + 1 < 12) {
            int kn = kc + 1;
            const float* Xs = (kn < 6) ? U : V;
            int kl = (kn < 6) ? kn : kn - 6;
            const float* xr = Xs + (row0 + arow)*T1 + kl*32 + akg;
            v0 = *(const float4*)xr; v1 = *(const float4*)(xr + 4);
        }
        CP_WAIT0();
        __syncthreads();
        if (kc + 1 < 12) {
            uint32_t nb = buf ^ 1;
            cvt_hilo_store(v0, v1,
                           (bf16*)(sm + nb*ABUF + aDstOff),
                           (bf16*)(sm + nb*ABUF + 5120 + aDstOff));
#pragma unroll
            for (int it = 0; it < 6; it++)
                CP16(sBbase + nb*BBUF + bDst[it], bSrc[it] + (kc + 1)*32);
            CP_COMMIT();
        }
        uint32_t aAddrH = sAbase + buf*ABUF + aOff;
        uint32_t aAddrL = aAddrH + 5120;
        uint32_t sBcur = sBbase + buf*BBUF;
#pragma unroll
        for (int k16 = 0; k16 < 2; k16++) {
            uint32_t kof = (uint32_t)(k16 * 32);
            uint32_t ah[4], al[4];
            LDM4(ah, aAddrH + kof);
            LDM4(al, aAddrL + kof);
            uint32_t baseH = sBcur + bOff + kof;
            uint32_t baseL = baseH + (uint32_t)(192*AST)*2;
#pragma unroll
            for (int pr = 0; pr < 6; pr++) {
                uint32_t po = (uint32_t)((wn*96 + pr*16)*AST)*2;
                uint32_t bh[4], bl[4];
                LDM4(bh, baseH + po);
                LDM4(bl, baseL + po);
                MMA_BF16(cc[2*pr],   ah, bh[0], bh[1]);
                MMA_BF16(cc[2*pr+1], ah, bh[2], bh[3]);
                MMA_BF16(cc[2*pr],   al, bh[0], bh[1]);
                MMA_BF16(cc[2*pr+1], al, bh[2], bh[3]);
                MMA_BF16(cc[2*pr],   ah, bl[0], bl[1]);
                MMA_BF16(cc[2*pr+1], ah, bl[2], bl[3]);
            }
        }
    }

    int g = lane >> 2, tg = lane & 3;
    size_t mrow = row0 + (size_t)wm*16 + g;
    int colb = wn*96 + tg*2;
#pragma unroll
    for (int nf = 0; nf < 12; nf++) {
        int col = colb + nf*8;
        float2 r0 = *(const float2*)&resid[mrow*T1 + col];
        float2 r1 = *(const float2*)&resid[(mrow + 8)*T1 + col];
        *(float2*)&Y[mrow*T1 + col]       = make_float2(cc[nf][0] + r0.x, cc[nf][1] + r0.y);
        *(float2*)&Y[(mrow + 8)*T1 + col] = make_float2(cc[nf][2] + r1.x, cc[nf][3] + r1.y);
    }
}

// ---------------- channel GEMM (tensor, cp.async pipeline): Y = (X1 + sg*X2) @ W[c] [+bias] ----------------
// dyn smem: sA [2][10240] @0 (20480), sB [2][15360] @20480 (30720), sg @51200 => 51968
template<int KTOT, bool BIAS>
__global__ void __launch_bounds__(256) k_cgemmMMA(const float* __restrict__ X1,
                                                  const float* __restrict__ X2,
                                                  const bf16* __restrict__ WB,
                                                  const float* __restrict__ bias,
                                                  const float* __restrict__ gate,
                                                  float* __restrict__ Y) {
    constexpr int AST = 40, KC = KTOT/32;
    constexpr uint32_t ABUF = 10240, BBUF = 15360;
    extern __shared__ char sm[];
    char* sBc = sm + 20480;
    float* sg = (float*)(sm + 51200);
    int tid = threadIdx.x, lane = tid & 31, wid = tid >> 5;
    int wm = wid & 3, wn = wid >> 2;
    int c = blockIdx.y, b = blockIdx.z;
    size_t row0 = (size_t)(b*CC + c)*NN + (size_t)blockIdx.x*64;
    const bf16* Wc = WB + (size_t)c*2*96*KTOT;

    for (int t = tid; t < KTOT; t += 256) sg[t] = 1.0f + gate[b*KTOT + t];
    __syncthreads();

    float cc[6][4];
#pragma unroll
    for (int i = 0; i < 6; i++)
#pragma unroll
        for (int j = 0; j < 4; j++) cc[i][j] = 0.f;

    uint32_t sAbase = smem_u32(sm);
    uint32_t sBbase = smem_u32(sBc);
    uint32_t aOff = (uint32_t)((wm*16 + (lane & 15))*AST + ((lane >> 4) << 3)) * 2;
    uint32_t bRow = (uint32_t)(wn*48 + (lane & 7) + ((lane >> 4) << 3));
    uint32_t bOff = (bRow*AST + (((lane >> 3) & 1) << 3)) * 2;

    int arow = tid >> 2, akg = (tid & 3) * 8;
    const float* x1r = X1 + (row0 + arow)*KTOT;
    const float* x2r = X2 + (row0 + arow)*KTOT;
    uint32_t aDstOff = (uint32_t)(arow*AST + akg) * 2;

    uint32_t bDst[3];
    const bf16* bSrc[3];
#pragma unroll
    for (int it = 0; it < 3; it++) {
        int i = tid + it*256;
        int plane = i / 384, rem = i % 384;
        int n = rem >> 2, kg = (rem & 3) * 8;
        bDst[it] = (uint32_t)((plane*96 + n)*AST + kg) * 2;
        bSrc[it] = &Wc[((size_t)plane*96 + n)*KTOT + kg];
    }

    // prologue: stage chunk 0
    {
        float4 v0 = *(const float4*)&x1r[akg];
        float4 v1 = *(const float4*)&x1r[akg + 4];
        float4 u0 = *(const float4*)&x2r[akg];
        float4 u1 = *(const float4*)&x2r[akg + 4];
        v0.x = fmaf(u0.x, sg[akg],   v0.x);
        v0.y = fmaf(u0.y, sg[akg+1], v0.y);
        v0.z = fmaf(u0.z, sg[akg+2], v0.z);
        v0.w = fmaf(u0.w, sg[akg+3], v0.w);
        v1.x = fmaf(u1.x, sg[akg+4], v1.x);
        v1.y = fmaf(u1.y, sg[akg+5], v1.y);
        v1.z = fmaf(u1.z, sg[akg+6], v1.z);
        v1.w = fmaf(u1.w, sg[akg+7], v1.w);
        cvt_hilo_store(v0, v1, (bf16*)(sm + aDstOff), (bf16*)(sm + 5120 + aDstOff));
#pragma unroll
        for (int it = 0; it < 3; it++) CP16(sBbase + bDst[it], bSrc[it]);
        CP_COMMIT();
    }

    for (int kc = 0; kc < KC; kc++) {
        uint32_t buf = (uint32_t)(kc & 1);
        float4 v0, v1, u0, u1;
        if (kc + 1 < KC) {
            int kn = (kc + 1)*32 + akg;
            v0 = *(const float4*)&x1r[kn];
            v1 = *(const float4*)&x1r[kn + 4];
            u0 = *(const float4*)&x2r[kn];
            u1 = *(const float4*)&x2r[kn + 4];
        }
        CP_WAIT0();
        __syncthreads();
        if (kc + 1 < KC) {
            uint32_t nb = buf ^ 1;
            int k0 = (kc + 1)*32 + akg;
            v0.x = fmaf(u0.x, sg[k0],   v0.x);
            v0.y = fmaf(u0.y, sg[k0+1], v0.y);
            v0.z = fmaf(u0.z, sg[k0+2], v0.z);
            v0.w = fmaf(u0.w, sg[k0+3], v0.w);
            v1.x = fmaf(u1.x, sg[k0+4], v1.x);
            v1.y = fmaf(u1.y, sg[k0+5], v1.y);
            v1.z = fmaf(u1.z, sg[k0+6], v1.z);
            v1.w = fmaf(u1.w, sg[k0+7], v1.w);
            cvt_hilo_store(v0, v1,
                           (bf16*)(sm + nb*ABUF + aDstOff),
                           (bf16*)(sm + nb*ABUF + 5120 + aDstOff));
#pragma unroll
            for (int it = 0; it < 3; it++)
                CP16(sBbase + nb*BBUF + bDst[it], bSrc[it] + (kc + 1)*32);
            CP_COMMIT();
        }
        uint32_t aAddrH = sAbase + buf*ABUF + aOff;
        uint32_t aAddrL = aAddrH + 5120;
        uint32_t sBcur = sBbase + buf*BBUF;
#pragma unroll
        for (int k16 = 0; k16 < 2; k16++) {
            uint32_t kof = (uint32_t)(k16 * 32);
            uint32_t ah[4], al[4];
            LDM4(ah, aAddrH + kof);
            LDM4(al, aAddrL + kof);
            uint32_t baseH = sBcur + bOff + kof;
            uint32_t baseL = baseH + (uint32_t)(96*AST)*2;
#pragma unroll
            for (int pr = 0; pr < 3; pr++) {
                uint32_t po = (uint32_t)(pr*16*AST)*2;
                uint32_t bh[4], bl[4];
                LDM4(bh, baseH + po);
                LDM4(bl, baseL + po);
                MMA_BF16(cc[2*pr],   ah, bh[0], bh[1]);
                MMA_BF16(cc[2*pr+1], ah, bh[2], bh[3]);
                MMA_BF16(cc[2*pr],   al, bh[0], bh[1]);
                MMA_BF16(cc[2*pr+1], al, bh[2], bh[3]);
                MMA_BF16(cc[2*pr],   ah, bl[0], bl[1]);
                MMA_BF16(cc[2*pr+1], ah, bl[2], bl[3]);
            }
        }
    }

    int g = lane >> 2, tg = lane & 3;
    size_t mrow = row0 + (size_t)wm*16 + g;
    int colb = wn*48 + tg*2;
#pragma unroll
    for (int nf = 0; nf < 6; nf++) {
        int col = colb + nf*8;
        float2 o0 = make_float2(cc[nf][0], cc[nf][1]);
        float2 o1 = make_float2(cc[nf][2], cc[nf][3]);
        if (BIAS) {
            float2 bv = *(const float2*)&bias[col];
            o0.x += bv.x; o0.y += bv.y; o1.x += bv.x; o1.y += bv.y;
        }
        *(float2*)&Y[mrow*96 + col]       = o0;
        *(float2*)&Y[(mrow + 8)*96 + col] = o1;
    }
}

// ---------------- tensor gmlp: cp.async double-buffered pipeline ----------------
// dyn smem: sA [2][hi 5120 | lo 5120] @0 (20480), sB [2][30720] @20480 (61440),
//           sg @81920 (<=768), sFP @82688 (1536)  => 84224
template<int KTOT, bool G1>
__global__ void __launch_bounds__(256) k_gmlpMMA(const float* __restrict__ X,
                                                 const bf16* __restrict__ Bw,
                                                 const float* __restrict__ gate,
                                                 float* __restrict__ Y) {
    constexpr int KC = KTOT/32;
    constexpr int AST = 40;
    constexpr uint32_t ABUF = 10240, BBUF = 30720;
    extern __shared__ char sm[];
    char* sBc = sm + 20480;
    float* sg = (float*)(sm + 81920);
    float (*sFP)[48] = (float(*)[48])(sm + 82688);
    int tid = threadIdx.x, lane = tid & 31, wid = tid >> 5;
    int wm = wid & 3, wn = wid >> 2;
    int half = blockIdx.y;
    int tix = blockIdx.x;
    size_t row0 = (size_t)tix * 64;
    int b = tix >> 8;
    int ch = (tix >> 3) & 31;
    int tile = tix & 7;
    const bf16* BwH = Bw + (size_t)half * 4*96*KTOT;

    if (G1) {
        for (int t = tid; t < KTOT; t += 256) sg[t] = 1.0f + gate[b*KTOT + t];
        __syncthreads();
    }

    float c1[6][4], c2[6][4];
#pragma unroll
    for (int i = 0; i < 6; i++)
#pragma unroll
        for (int j = 0; j < 4; j++) { c1[i][j] = 0.f; c2[i][j] = 0.f; }

    uint32_t sAbase = smem_u32(sm);
    uint32_t sBbase = smem_u32(sBc);
    uint32_t aOff = (uint32_t)((wm*16 + (lane & 15))*AST + ((lane >> 4) << 3)) * 2;
    uint32_t bRow = (uint32_t)(wn*48 + (lane & 7) + ((lane >> 4) << 3));
    uint32_t bOff = (bRow*AST + (((lane >> 3) & 1) << 3)) * 2;

    int arow = tid >> 2, akg = (tid & 3) * 8;
    const float* xrow = X + (row0 + arow)*KTOT;
    uint32_t aDstOff = (uint32_t)(arow*AST + akg) * 2;

    uint32_t bDst[6];
    const bf16* bSrc[6];
#pragma unroll
    for (int it = 0; it < 6; it++) {
        int i = tid + it*256;
        int mat = i / 384, rem = i % 384;
        int n = rem >> 2, kg = (rem & 3) * 8;
        bDst[it] = (uint32_t)((mat*96 + n)*AST + kg) * 2;
        bSrc[it] = &BwH[((size_t)mat*96 + n)*KTOT + kg];
    }

    // prologue: stage chunk 0 into buffer 0
    {
        float4 v0 = *(const float4*)&xrow[akg];
        float4 v1 = *(const float4*)&xrow[akg + 4];
        if (G1) {
            v0.x *= sg[akg];   v0.y *= sg[akg+1]; v0.z *= sg[akg+2]; v0.w *= sg[akg+3];
            v1.x *= sg[akg+4]; v1.y *= sg[akg+5]; v1.z *= sg[akg+6]; v1.w *= sg[akg+7];
        }
        cvt_hilo_store(v0, v1, (bf16*)(sm + aDstOff), (bf16*)(sm + 5120 + aDstOff));
#pragma unroll
        for (int it = 0; it < 6; it++) CP16(sBbase + bDst[it], bSrc[it]);
        CP_COMMIT();
    }

    for (int kc = 0; kc < KC; kc++) {
        uint32_t buf = (uint32_t)(kc & 1);
        float4 v0, v1;
        if (kc + 1 < KC) {
            int kn = (kc + 1)*32;
            v0 = *(const float4*)&xrow[kn + akg];
            v1 = *(const float4*)&xrow[kn + akg + 4];
        }
        CP_WAIT0();
        __syncthreads();
        if (kc + 1 < KC) {
            uint32_t nb = buf ^ 1;
            int k0 = (kc + 1)*32 + akg;
            if (G1) {
                v0.x *= sg[k0];   v0.y *= sg[k0+1]; v0.z *= sg[k0+2]; v0.w *= sg[k0+3];
                v1.x *= sg[k0+4]; v1.y *= sg[k0+5]; v1.z *= sg[k0+6]; v1.w *= sg[k0+7];
            }
            cvt_hilo_store(v0, v1,
                           (bf16*)(sm + nb*ABUF + aDstOff),
                           (bf16*)(sm + nb*ABUF + 5120 + aDstOff));
#pragma unroll
            for (int it = 0; it < 6; it++)
                CP16(sBbase + nb*BBUF + bDst[it], bSrc[it] + (kc + 1)*32);
            CP_COMMIT();
        }
        uint32_t aAddrH = sAbase + buf*ABUF + aOff;
        uint32_t aAddrL = aAddrH + 5120;
        uint32_t sBcur = sBbase + buf*BBUF;
#pragma unroll
        for (int k16 = 0; k16 < 2; k16++) {
            uint32_t kof = (uint32_t)(k16 * 32);
            uint32_t ah[4], al[4];
            LDM4(ah, aAddrH + kof);
            LDM4(al, aAddrL + kof);
#pragma unroll
            for (int mat = 0; mat < 2; mat++) {
                float (*cf)[4] = mat ? c2 : c1;
                uint32_t baseH = sBcur + (uint32_t)((mat*2 + 0)*96*AST)*2 + bOff + kof;
                uint32_t baseL = sBcur + (uint32_t)((mat*2 + 1)*96*AST)*2 + bOff + kof;
#pragma unroll
                for (int pr = 0; pr < 3; pr++) {
                    uint32_t po = (uint32_t)(pr*16*AST)*2;
                    uint32_t bh[4], bl[4];
                    LDM4(bh, baseH + po);
                    LDM4(bl, baseL + po);
                    MMA_BF16(cf[2*pr],   ah, bh[0], bh[1]);
                    MMA_BF16(cf[2*pr+1], ah, bh[2], bh[3]);
                    MMA_BF16(cf[2*pr],   al, bh[0], bh[1]);
                    MMA_BF16(cf[2*pr+1], al, bh[2], bh[3]);
                    MMA_BF16(cf[2*pr],   ah, bl[0], bl[1]);
                    MMA_BF16(cf[2*pr+1], ah, bl[2], bl[3]);
                }
            }
        }
    }

    // epilogue: o = (X@W1)*gelu(X@W2), store + column partial sums
    __syncthreads();
    int g = lane >> 2, tg = lane & 3;
    size_t mrow = row0 + (size_t)wm*16 + g;
    int colb = half*96 + wn*48 + tg*2;
    float colsum[12];
#pragma unroll
    for (int nf = 0; nf < 6; nf++) {
        int col = colb + nf*8;
        float2 o0 = make_float2(c1[nf][0]*gelu_t(c2[nf][0]), c1[nf][1]*gelu_t(c2[nf][1]));
        float2 o1 = make_float2(c1[nf][2]*gelu_t(c2[nf][2]), c1[nf][3]*gelu_t(c2[nf][3]));
        *(float2*)&Y[mrow*KTOT + col] = o0;
        *(float2*)&Y[(mrow + 8)*KTOT + col] = o1;
        colsum[2*nf]   = o0.x + o1.x;
        colsum[2*nf+1] = o0.y + o1.y;
    }
#pragma unroll
    for (int i = 0; i < 12; i++) {
        float v = colsum[i];
        v += __shfl_xor_sync(0xFFFFFFFF, v, 16);
        v += __shfl_xor_sync(0xFFFFFFFF, v, 8);
        v += __shfl_xor_sync(0xFFFFFFFF, v, 4);
        colsum[i] = v;
    }
    if (lane < 4) {
#pragma unroll
        for (int nf = 0; nf < 6; nf++) {
            sFP[wid][lane*2 + nf*8]     = colsum[2*nf];
            sFP[wid][lane*2 + nf*8 + 1] = colsum[2*nf+1];
        }
    }
    __syncthreads();
    if (tid < 96) {
        int wn2 = tid / 48, idx = tid % 48;
        float tot = sFP[wn2*4+0][idx] + sFP[wn2*4+1][idx] + sFP[wn2*4+2][idx] + sFP[wn2*4+3][idx];
        g_featP[((size_t)(b*CC + ch)*8 + tile)*KTOT + half*96 + wn2*48 + idx] = tot;
    }
}

// ---------------- attn gate (reads featP partials, 8 tiles) ----------------
template<int T>
__global__ void __launch_bounds__(T) k_gate(const float* __restrict__ Wq,
                                            const float* __restrict__ Wk) {
    __shared__ float ks[T][EE];
    int b = blockIdx.x, t = threadIdx.x;
    float q[EE], kk[EE];
#pragma unroll
    for (int e = 0; e < EE; e++) { q[e] = 0.f; kk[e] = 0.f; }
    for (int c = 0; c < CC; c++) {
        float f = 0.f;
#pragma unroll
        for (int p = 0; p < 8; p++) f += g_featP[((size_t)(b*CC + c)*8 + p)*T + t];
        f *= (1.0f/NN);
#pragma unroll
        for (int e = 0; e < EE; e++) {
            q[e]  = fmaf(f, Wq[c*EE + e], q[e]);
            kk[e] = fmaf(f, Wk[c*EE + e], kk[e]);
        }
    }
#pragma unroll
    for (int e = 0; e < EE; e++) ks[t][e] = kk[e];
    __syncthreads();
    float smax = -1e30f, stt = 0.f;
    for (int j = 0; j < T; j++) {
        float d = 0.f;
#pragma unroll
        for (int e = 0; e < EE; e++) d = fmaf(q[e], ks[j][e], d);
        d *= 0.125f;
        if (j == t) stt = d;
        smax = fmaxf(smax, d);
    }
    float ssum = 0.f;
    for (int j = 0; j < T; j++) {
        float d = 0.f;
#pragma unroll
        for (int e = 0; e < EE; e++) d = fmaf(q[e], ks[j][e], d);
        ssum += expf(d*0.125f - smax);
    }
    float p = expf(stt - smax) / ssum;
    g_gate[b*T + t] = gelu_t(p);
}

// ---------------- driver ----------------
extern "C" void kernel_launch(void* const* d_in, const int* in_sizes, int n_in,
                              void* d_out, int out_size) {
    const float* x   = (const float*)d_in[0];
    const float* Gc  = (const float*)d_in[3];
    const float* Lc  = (const float*)d_in[4];
    const float* Gt  = (const float*)d_in[5];
    const float* Lt  = (const float*)d_in[6];
    const float* f1r = (const float*)d_in[7];
    const float* f1i = (const float*)d_in[8];
    const float* f2r = (const float*)d_in[9];
    const float* f2i = (const float*)d_in[10];
    const float* Wfc = (const float*)d_in[11];
    const float* bfc = (const float*)d_in[12];
    const float* mi1 = (const float*)d_in[13];
    const float* mi2 = (const float*)d_in[14];
    const float* mo1 = (const float*)d_in[15];
    const float* mo2 = (const float*)d_in[16];
    const float* aiq = (const float*)d_in[17];
    const float* aik = (const float*)d_in[18];
    const float* aoq = (const float*)d_in[19];
    const float* aok = (const float*)d_in[20];
    float* out = (float*)d_out;

    float *bufA, *bufB, *bufC, *bufD, *bufF, *gate;
    bf16 *Bin, *Bout, *D1B, *C2B;
    cudaGetSymbolAddress((void**)&bufA, g_bufA);
    cudaGetSymbolAddress((void**)&bufB, g_bufB);
    cudaGetSymbolAddress((void**)&bufC, g_bufC);
    cudaGetSymbolAddress((void**)&bufD, g_bufD);
    cudaGetSymbolAddress((void**)&bufF, g_bufF);
    cudaGetSymbolAddress((void**)&gate, g_gate);
    cudaGetSymbolAddress((void**)&Bin,  g_Bin);
    cudaGetSymbolAddress((void**)&Bout, g_Bout);
    cudaGetSymbolAddress((void**)&D1B,  g_D1B);
    cudaGetSymbolAddress((void**)&C2B,  g_C2B);

    constexpr int SMEM_G = 84224;
    constexpr int SMEM_M = 81920;
    constexpr int SMEM_C = 51968;
    cudaFuncSetAttribute(k_gmlpMMA<T1,false>, cudaFuncAttributeMaxDynamicSharedMemorySize, SMEM_G);
    cudaFuncSetAttribute(k_gmlpMMA<T1,true >, cudaFuncAttributeMaxDynamicSharedMemorySize, SMEM_G);
    cudaFuncSetAttribute(k_gmlpMMA<T2,false>, cudaFuncAttributeMaxDynamicSharedMemorySize, SMEM_G);
    cudaFuncSetAttribute(k_gmlpMMA<T2,true >, cudaFuncAttributeMaxDynamicSharedMemorySize, SMEM_G);
    cudaFuncSetAttribute(k_mm2MMA, cudaFuncAttributeMaxDynamicSharedMemorySize, SMEM_M);
    cudaFuncSetAttribute(k_cgemmMMA<T1,true >, cudaFuncAttributeMaxDynamicSharedMemorySize, SMEM_C);
    cudaFuncSetAttribute(k_cgemmMMA<T2,false>, cudaFuncAttributeMaxDynamicSharedMemorySize, SMEM_C);

    // launch order puts k_mm2MMA at index 3 so ncu's capture slot profiles it.
    k_tables<<<(L1*T1 + L2*T2 + 255)/256, 256>>>();                     // 0
    k_buildMB<<<dim3(T1, CC), T1>>>(Lc, Lt);                            // 1 (fused buildM+splitMM)
    k_chmix<<<dim3(NN*T1/256, BB), 256>>>(x, Gc, Gt);                   // 2
    k_mm2MMA<<<dim3(NN/64, CC, BB), 256, SMEM_M>>>(bufA, bufB, x, bufC); // 3  <- profiled

    // remaining precompute (independent of mm2)
    k_splitW<T1,2><<<(2*2*4*96*T1 + 255)/256, 256>>>(mi1, mi2, Bin);
    k_buildK1<<<(CC*T1 + 255)/256, 256>>>(f1r, f1i);
    k_buildD1B<<<dim3(T2, CC), T1>>>(Wfc);
    k_buildK2<<<(CC*T2 + 255)/256, 256>>>(f2r, f2i);
    k_buildC2B<<<dim3(T2, CC), T2>>>();
    k_splitW<T2,1><<<(2*1*4*96*T2 + 255)/256, 256>>>(mo1, mo2, Bout);

    const int NT = BB*CC*NN/64;               // 4096 M-tiles of 64 rows
    const size_t L1OFF = (size_t)2*4*96*T1;
    const size_t L2OFF = (size_t)1*4*96*T2;

    // input-side layers (tensor core, cp.async pipeline, n-mean fused)
    k_gmlpMMA<T1,false><<<dim3(NT, 2), 256, SMEM_G>>>(bufC, Bin, nullptr, bufA);
    k_gate<T1><<<BB, T1>>>(aiq, aik);
    k_gmlpMMA<T1,true ><<<dim3(NT, 2), 256, SMEM_G>>>(bufA, Bin + L1OFF, gate, bufC);
    k_gate<T1><<<BB, T1>>>(aiq + CC*EE, aik + CC*EE);

    // h_y = (x + xc*(1+g)) @ D1[c] + bfc   (fconv1 + fc_idp fused, tensor, pipelined)
    k_cgemmMMA<T1, true><<<dim3(NN/64, CC, BB), 256, SMEM_C>>>(x, bufC, D1B, bfc, gate, bufD);

    // output-side layers (tensor core, cp.async pipeline, n-mean fused)
    k_gmlpMMA<T2,false><<<dim3(NT, 1), 256, SMEM_G>>>(bufD, Bout, nullptr, bufA);
    k_gate<T2><<<BB, T2>>>(aoq, aok);
    k_gmlpMMA<T2,true ><<<dim3(NT, 1), 256, SMEM_G>>>(bufA, Bout + L2OFF, gate, bufF);
    k_gate<T2><<<BB, T2>>>(aoq + CC*EE, aok + CC*EE);

    // out = (h_y + y_c*(1+g)) @ C2[c]   (tensor, pipelined)
    k_cgemmMMA<T2, false><<<dim3(NN/64, CC, BB), 256, SMEM_C>>>(bufD, bufF, C2B, nullptr, gate, out);
}